// round 3
// baseline (speedup 1.0000x reference)
#include <cuda_runtime.h>
#include <math.h>

#define B_ 16
#define T_ 512
#define D_ 256
#define H_ 8
#define E_ 32
#define BASIS_ 8
#define HB_ 128          // H_*B_
#define HE_ 256          // H_*E_
#define R_CACHE 104      // sinkhorn smem-cached rows

// ---------------- scratch (static device globals; no allocation) ----------------
__device__ float g_qw[T_*BASIS_];
__device__ float g_kw[T_*BASIS_];
__device__ float g_Qt[T_*D_*HE_];      // 134MB
__device__ float g_Kt[T_*D_*HE_];      // 134MB
__device__ float g_q[HB_*T_*E_];       // [h][b][t][e]
__device__ float g_k[HB_*T_*E_];
__device__ float g_v[HB_*T_*E_];
__device__ float g_lamA[T_*T_];
__device__ float g_oml[T_*T_];
__device__ float g_M[HB_*T_*T_];       // 134MB  (mixed att, pre-symmetrization)
__device__ float g_EE[HB_*T_*T_];      // 134MB  exp(att_sym)
__device__ float g_eu[HB_*T_];
__device__ float g_ev[HB_*T_];

// ---------------- K1: per-token basis mixing weights ----------------
// qw[t,k] = sum_d te[t,d]*Wq[t,k,d]   (one warp per (t,k))
__global__ void k1_weights(const float* __restrict__ te,
                           const float* __restrict__ Wq,
                           const float* __restrict__ Wk) {
    int t = blockIdx.x;
    int warp = threadIdx.x >> 5, lane = threadIdx.x & 31;
    const float* tr = te + t * D_;
    const float* wq = Wq + (t * BASIS_ + warp) * D_;
    const float* wk = Wk + (t * BASIS_ + warp) * D_;
    float aq = 0.f, ak = 0.f;
    #pragma unroll
    for (int m = 0; m < D_ / 32; ++m) {
        int d = lane + 32 * m;
        float x = tr[d];
        aq += x * wq[d];
        ak += x * wk[d];
    }
    #pragma unroll
    for (int o = 16; o; o >>= 1) {
        aq += __shfl_xor_sync(0xffffffffu, aq, o);
        ak += __shfl_xor_sync(0xffffffffu, ak, o);
    }
    if (lane == 0) {
        g_qw[t * BASIS_ + warp] = aq;
        g_kw[t * BASIS_ + warp] = ak;
    }
}

// ---------------- K2: Q_tilde / K_tilde build ----------------
// out[t, f] = sum_k w[t,k] * basis[k, f],  f = d*HE+e  (basis kept in registers, loop t)
__global__ void k2_tilde(const float* __restrict__ Qb, const float* __restrict__ Kb) {
    __shared__ float sW[T_ * BASIS_];
    int qk = blockIdx.y;
    const float* W = qk ? g_kw : g_qw;
    const float* Bs = qk ? Kb : Qb;
    float* Out = qk ? g_Kt : g_Qt;
    for (int idx = threadIdx.x; idx < T_ * BASIS_; idx += blockDim.x) sW[idx] = W[idx];
    __syncthreads();

    int f4 = blockIdx.x * blockDim.x + threadIdx.x;   // float4 index, 16384 total
    float4 b4[BASIS_];
    #pragma unroll
    for (int k = 0; k < BASIS_; ++k) b4[k] = ((const float4*)Bs)[k * 16384 + f4];

    for (int t = 0; t < T_; ++t) {
        float4 a = make_float4(0.f, 0.f, 0.f, 0.f);
        #pragma unroll
        for (int k = 0; k < BASIS_; ++k) {
            float w = sW[t * BASIS_ + k];
            a.x += w * b4[k].x; a.y += w * b4[k].y;
            a.z += w * b4[k].z; a.w += w * b4[k].w;
        }
        ((float4*)Out)[t * 16384 + f4] = a;
    }
}

// ---------------- K3: per-token q/k/v projections ----------------
// per token t: [16,256] @ [256,256] -> scatter to [h][b][t][e]
__global__ __launch_bounds__(256) void k3_qkv(const float* __restrict__ X,
                                              const float* __restrict__ WV) {
    __shared__ float xsT[D_][16];
    int t = blockIdx.x, m = blockIdx.y;
    const float* W = (m == 0) ? (g_Qt + (size_t)t * 65536)
                   : (m == 1) ? (g_Kt + (size_t)t * 65536)
                              : (WV + (size_t)t * 65536);
    float* Out = (m == 0) ? g_q : (m == 1) ? g_k : g_v;

    for (int idx = threadIdx.x; idx < B_ * D_; idx += blockDim.x) {
        int b = idx >> 8, d = idx & 255;
        xsT[d][b] = X[((size_t)b * T_ + t) * D_ + d];
    }
    __syncthreads();

    int tb = threadIdx.x >> 6;   // 0..3  -> b base = 4*tb
    int tc = threadIdx.x & 63;   // 0..63 -> col base = 4*tc
    float acc[4][4];
    #pragma unroll
    for (int i = 0; i < 4; ++i)
        #pragma unroll
        for (int j = 0; j < 4; ++j) acc[i][j] = 0.f;

    #pragma unroll 4
    for (int d = 0; d < D_; ++d) {
        float4 xv = *(const float4*)&xsT[d][tb << 2];
        float4 wv = *(const float4*)&W[d * HE_ + (tc << 2)];
        acc[0][0] += xv.x * wv.x; acc[0][1] += xv.x * wv.y; acc[0][2] += xv.x * wv.z; acc[0][3] += xv.x * wv.w;
        acc[1][0] += xv.y * wv.x; acc[1][1] += xv.y * wv.y; acc[1][2] += xv.y * wv.z; acc[1][3] += xv.y * wv.w;
        acc[2][0] += xv.z * wv.x; acc[2][1] += xv.z * wv.y; acc[2][2] += xv.z * wv.z; acc[2][3] += xv.z * wv.w;
        acc[3][0] += xv.w * wv.x; acc[3][1] += xv.w * wv.y; acc[3][2] += xv.w * wv.z; acc[3][3] += xv.w * wv.w;
    }

    int e0 = tc << 2;
    int h = e0 >> 5, eo = e0 & 31;
    #pragma unroll
    for (int i = 0; i < 4; ++i) {
        int b = (tb << 2) + i;
        float4 r = make_float4(acc[i][0], acc[i][1], acc[i][2], acc[i][3]);
        *(float4*)&Out[(((h * B_ + b) * T_ + t) << 5) + eo] = r;
    }
}

// ---------------- K4: mixing coefficients ----------------
__global__ void k4_mix(const float* __restrict__ A, const float* __restrict__ L) {
    int t = blockIdx.x, s = threadIdx.x;
    float a = A[t * T_ + s], at = A[s * T_ + t];
    float lam = 1.0f / (1.0f + __expf(-L[t * T_ + s]));
    g_lamA[t * T_ + s] = lam * 0.5f * (a + at);
    g_oml[t * T_ + s] = 1.0f - lam;
}

// ---------------- K5: scores + softmax + mixing -> M ----------------
__global__ __launch_bounds__(256) void k5_scores() {
    extern __shared__ float kT[];   // [32][513] padded transpose of K
    int hb = blockIdx.x;
    const float* K = g_k + hb * (T_ * E_);
    const float* Q = g_q + hb * (T_ * E_);
    float* M = g_M + (size_t)hb * T_ * T_;

    for (int idx = threadIdx.x; idx < T_ * E_; idx += blockDim.x) {
        int s = idx >> 5, d = idx & 31;
        kT[d * 513 + s] = K[idx];
    }
    __syncthreads();

    int warp = threadIdx.x >> 5, lane = threadIdx.x & 31;
    const float SC = 0.17677669529663687f;  // 1/sqrt(32)

    for (int i = warp; i < T_; i += 8) {
        float q = Q[i * E_ + lane];
        float acc[16];
        #pragma unroll
        for (int s = 0; s < 16; ++s) acc[s] = 0.f;
        #pragma unroll
        for (int d = 0; d < 32; ++d) {
            float qd = __shfl_sync(0xffffffffu, q, d);
            #pragma unroll
            for (int s = 0; s < 16; ++s) acc[s] += qd * kT[d * 513 + lane + (s << 5)];
        }
        float mx = -1e30f;
        #pragma unroll
        for (int s = 0; s < 16; ++s) { acc[s] *= SC; mx = fmaxf(mx, acc[s]); }
        #pragma unroll
        for (int o = 16; o; o >>= 1) mx = fmaxf(mx, __shfl_xor_sync(0xffffffffu, mx, o));
        float sum = 0.f;
        #pragma unroll
        for (int s = 0; s < 16; ++s) { acc[s] = __expf(acc[s] - mx); sum += acc[s]; }
        #pragma unroll
        for (int o = 16; o; o >>= 1) sum += __shfl_xor_sync(0xffffffffu, sum, o);
        float inv = 1.0f / sum;
        #pragma unroll
        for (int s = 0; s < 16; ++s) {
            int j = lane + (s << 5);
            int idx = i * T_ + j;
            M[idx] = g_lamA[idx] + g_oml[idx] * (acc[s] * inv);
        }
    }
}

// ---------------- K6: symmetrize + exp -> EE ----------------
__global__ void k6_symexp() {
    __shared__ float sA[32][33], sB[32][33];
    int ti = blockIdx.y, tj = blockIdx.z;
    if (tj < ti) return;
    int hb = blockIdx.x;
    const float* M = g_M + (size_t)hb * T_ * T_;
    float* E = g_EE + (size_t)hb * T_ * T_;
    int tx = threadIdx.x, ty = threadIdx.y;
    sA[ty][tx] = M[(ti * 32 + ty) * T_ + tj * 32 + tx];
    sB[ty][tx] = M[(tj * 32 + ty) * T_ + ti * 32 + tx];
    __syncthreads();
    E[(ti * 32 + ty) * T_ + tj * 32 + tx] = __expf(0.5f * (sA[ty][tx] + sB[tx][ty]));
    E[(tj * 32 + ty) * T_ + ti * 32 + tx] = __expf(0.5f * (sB[ty][tx] + sA[tx][ty]));
}

// ---------------- K7: all 20 Sinkhorn iterations, one CTA per (h,b) matrix ----------------
// linear-domain equivalence: eu_i = 1/sum_j E_ij*ev_j ; ev_j = 1/sum_i E_ij*eu_i
__global__ __launch_bounds__(512) void k7_sinkhorn() {
    extern __shared__ float sm[];
    float* sEE = sm;                       // R_CACHE x 512
    float* s_eu = sm + R_CACHE * 512;      // 512
    float* s_ev = s_eu + 512;              // 512
    int hb = blockIdx.x;
    const float* E = g_EE + (size_t)hb * T_ * T_;
    int tid = threadIdx.x;

    // cache top rows in smem
    for (int idx = tid; idx < R_CACHE * 128; idx += 512)
        ((float4*)sEE)[idx] = ((const float4*)E)[idx];
    s_ev[tid] = 1.0f;
    __syncthreads();

    int warp = tid >> 5, lane = tid & 31;

    for (int it = 0; it < 20; ++it) {
        // ---- u-step: row sums (warp per row) ----
        for (int i = warp; i < T_; i += 16) {
            float acc = 0.f;
            if (i < R_CACHE) {
                const float* row = sEE + i * 512;
                #pragma unroll
                for (int m = 0; m < 4; ++m) {
                    int j = (lane << 2) + (m << 7);
                    float4 e4 = *(const float4*)(row + j);
                    float4 v4 = *(const float4*)(s_ev + j);
                    acc += e4.x * v4.x + e4.y * v4.y + e4.z * v4.z + e4.w * v4.w;
                }
            } else {
                const float* row = E + i * 512;
                #pragma unroll
                for (int m = 0; m < 4; ++m) {
                    int j = (lane << 2) + (m << 7);
                    float4 e4 = *(const float4*)(row + j);
                    float4 v4 = *(const float4*)(s_ev + j);
                    acc += e4.x * v4.x + e4.y * v4.y + e4.z * v4.z + e4.w * v4.w;
                }
            }
            #pragma unroll
            for (int o = 16; o; o >>= 1) acc += __shfl_xor_sync(0xffffffffu, acc, o);
            if (lane == 0) s_eu[i] = 1.0f / acc;
        }
        __syncthreads();

        // ---- v-step: column sums (thread per column) ----
        float s = 0.f;
        #pragma unroll 4
        for (int i = 0; i < R_CACHE; ++i) s += sEE[i * 512 + tid] * s_eu[i];
        #pragma unroll 2
        for (int i = R_CACHE; i < T_; i += 4) {
            s += E[(size_t)i * 512 + tid] * s_eu[i]
               + E[(size_t)(i + 1) * 512 + tid] * s_eu[i + 1]
               + E[(size_t)(i + 2) * 512 + tid] * s_eu[i + 2]
               + E[(size_t)(i + 3) * 512 + tid] * s_eu[i + 3];
        }
        s_ev[tid] = 1.0f / s;
        __syncthreads();
    }

    g_eu[hb * T_ + tid] = s_eu[tid];
    g_ev[hb * T_ + tid] = s_ev[tid];
}

// ---------------- K8: out = (E*eu*ev) @ V, write [B,T,D] ----------------
__global__ __launch_bounds__(256) void k8_out(float* __restrict__ out) {
    extern __shared__ float Ws[];   // [512][33] : V row-scaled by ev
    int hb = blockIdx.x, rb = blockIdx.y;
    int h = hb >> 4, b = hb & 15;
    const float* E = g_EE + (size_t)hb * T_ * T_;
    const float* V = g_v + hb * (T_ * E_);
    const float* ev = g_ev + hb * T_;
    const float* eu = g_eu + hb * T_;

    for (int idx = threadIdx.x; idx < T_ * E_; idx += blockDim.x) {
        int s = idx >> 5, e = idx & 31;
        Ws[s * 33 + e] = V[idx] * ev[s];
    }
    __syncthreads();

    int warp = threadIdx.x >> 5, lane = threadIdx.x & 31;
    for (int r = 0; r < 8; ++r) {
        int i = rb * 64 + warp * 8 + r;
        float acc[32];
        #pragma unroll
        for (int e = 0; e < 32; ++e) acc[e] = 0.f;
        #pragma unroll 2
        for (int m = 0; m < 16; ++m) {
            int s = lane + (m << 5);
            float ee = E[i * T_ + s];
            #pragma unroll
            for (int e = 0; e < 32; ++e) acc[e] += ee * Ws[s * 33 + e];
        }
        float res = 0.f;
        #pragma unroll
        for (int e = 0; e < 32; ++e) {
            float v = acc[e];
            #pragma unroll
            for (int o = 16; o; o >>= 1) v += __shfl_xor_sync(0xffffffffu, v, o);
            if (lane == e) res = v;
        }
        out[(((size_t)b * T_ + i) << 8) + (h << 5) + lane] = eu[i] * res;
    }
}

// ---------------- launch ----------------
extern "C" void kernel_launch(void* const* d_in, const int* in_sizes, int n_in,
                              void* d_out, int out_size) {
    const float* X  = (const float*)d_in[0];
    const float* te = (const float*)d_in[1];
    const float* Wq = (const float*)d_in[2];
    const float* Wk = (const float*)d_in[3];
    const float* Qb = (const float*)d_in[4];
    const float* Kb = (const float*)d_in[5];
    const float* WV = (const float*)d_in[6];
    const float* A  = (const float*)d_in[7];
    const float* L  = (const float*)d_in[8];
    float* out = (float*)d_out;

    const int smem5 = 32 * 513 * 4;                 // 65664
    const int smem7 = (R_CACHE * 512 + 1024) * 4;   // 217088
    const int smem8 = 512 * 33 * 4;                 // 67584
    cudaFuncSetAttribute(k5_scores,   cudaFuncAttributeMaxDynamicSharedMemorySize, smem5);
    cudaFuncSetAttribute(k7_sinkhorn, cudaFuncAttributeMaxDynamicSharedMemorySize, smem7);
    cudaFuncSetAttribute(k8_out,      cudaFuncAttributeMaxDynamicSharedMemorySize, smem8);

    k1_weights<<<T_, 256>>>(te, Wq, Wk);
    k2_tilde<<<dim3(64, 2), 256>>>(Qb, Kb);
    k3_qkv<<<dim3(T_, 3), 256>>>(X, WV);
    k4_mix<<<T_, T_>>>(A, L);
    k5_scores<<<HB_, 256, smem5>>>();
    k6_symexp<<<dim3(HB_, 16, 16), dim3(32, 32)>>>();
    k7_sinkhorn<<<HB_, 512, smem7>>>();
    k8_out<<<dim3(HB_, 8), 256, smem8>>>(out);
}

// round 4
// speedup vs baseline: 1.5885x; 1.5885x over previous
#include <cuda_runtime.h>
#include <cuda_fp16.h>
#include <math.h>

#define B_ 16
#define T_ 512
#define D_ 256
#define H_ 8
#define E_ 32
#define BASIS_ 8
#define HB_ 128          // H_*B_
#define HE_ 256          // H_*E_

// ---------------- scratch (static device globals; no allocation) ----------------
__device__ float g_qw[T_*BASIS_];
__device__ float g_kw[T_*BASIS_];
__device__ float g_Qt[T_*D_*HE_];      // 134MB
__device__ float g_Kt[T_*D_*HE_];      // 134MB
__device__ float g_q[HB_*T_*E_];       // [h][b][t][e]
__device__ float g_k[HB_*T_*E_];
__device__ float g_v[HB_*T_*E_];
__device__ float g_lamA[T_*T_];
__device__ float g_oml[T_*T_];
__device__ float g_M[HB_*T_*T_];       // 134MB  (mixed att, pre-symmetrization)
__device__ float g_EE[HB_*T_*T_];      // 134MB  exp(att_sym)
__device__ float g_eu[HB_*T_];
__device__ float g_ev[HB_*T_];

// ---------------- K1: per-token basis mixing weights ----------------
__global__ void k1_weights(const float* __restrict__ te,
                           const float* __restrict__ Wq,
                           const float* __restrict__ Wk) {
    int t = blockIdx.x;
    int warp = threadIdx.x >> 5, lane = threadIdx.x & 31;
    const float* tr = te + t * D_;
    const float* wq = Wq + (t * BASIS_ + warp) * D_;
    const float* wk = Wk + (t * BASIS_ + warp) * D_;
    float aq = 0.f, ak = 0.f;
    #pragma unroll
    for (int m = 0; m < D_ / 32; ++m) {
        int d = lane + 32 * m;
        float x = tr[d];
        aq += x * wq[d];
        ak += x * wk[d];
    }
    #pragma unroll
    for (int o = 16; o; o >>= 1) {
        aq += __shfl_xor_sync(0xffffffffu, aq, o);
        ak += __shfl_xor_sync(0xffffffffu, ak, o);
    }
    if (lane == 0) {
        g_qw[t * BASIS_ + warp] = aq;
        g_kw[t * BASIS_ + warp] = ak;
    }
}

// ---------------- K2: Q_tilde / K_tilde build ----------------
__global__ void k2_tilde(const float* __restrict__ Qb, const float* __restrict__ Kb) {
    __shared__ float sW[T_ * BASIS_];
    int qk = blockIdx.y;
    const float* W = qk ? g_kw : g_qw;
    const float* Bs = qk ? Kb : Qb;
    float* Out = qk ? g_Kt : g_Qt;
    for (int idx = threadIdx.x; idx < T_ * BASIS_; idx += blockDim.x) sW[idx] = W[idx];
    __syncthreads();

    int f4 = blockIdx.x * blockDim.x + threadIdx.x;   // float4 index, 16384 total
    float4 b4[BASIS_];
    #pragma unroll
    for (int k = 0; k < BASIS_; ++k) b4[k] = ((const float4*)Bs)[k * 16384 + f4];

    for (int t = 0; t < T_; ++t) {
        float4 a = make_float4(0.f, 0.f, 0.f, 0.f);
        #pragma unroll
        for (int k = 0; k < BASIS_; ++k) {
            float w = sW[t * BASIS_ + k];
            a.x += w * b4[k].x; a.y += w * b4[k].y;
            a.z += w * b4[k].z; a.w += w * b4[k].w;
        }
        ((float4*)Out)[t * 16384 + f4] = a;
    }
}

// ---------------- K3: per-token q/k/v projections ----------------
__global__ __launch_bounds__(256) void k3_qkv(const float* __restrict__ X,
                                              const float* __restrict__ WV) {
    __shared__ float xsT[D_][16];
    int t = blockIdx.x, m = blockIdx.y;
    const float* W = (m == 0) ? (g_Qt + (size_t)t * 65536)
                   : (m == 1) ? (g_Kt + (size_t)t * 65536)
                              : (WV + (size_t)t * 65536);
    float* Out = (m == 0) ? g_q : (m == 1) ? g_k : g_v;

    for (int idx = threadIdx.x; idx < B_ * D_; idx += blockDim.x) {
        int b = idx >> 8, d = idx & 255;
        xsT[d][b] = X[((size_t)b * T_ + t) * D_ + d];
    }
    __syncthreads();

    int tb = threadIdx.x >> 6;   // 0..3
    int tc = threadIdx.x & 63;   // 0..63
    float acc[4][4];
    #pragma unroll
    for (int i = 0; i < 4; ++i)
        #pragma unroll
        for (int j = 0; j < 4; ++j) acc[i][j] = 0.f;

    #pragma unroll 4
    for (int d = 0; d < D_; ++d) {
        float4 xv = *(const float4*)&xsT[d][tb << 2];
        float4 wv = *(const float4*)&W[d * HE_ + (tc << 2)];
        acc[0][0] += xv.x * wv.x; acc[0][1] += xv.x * wv.y; acc[0][2] += xv.x * wv.z; acc[0][3] += xv.x * wv.w;
        acc[1][0] += xv.y * wv.x; acc[1][1] += xv.y * wv.y; acc[1][2] += xv.y * wv.z; acc[1][3] += xv.y * wv.w;
        acc[2][0] += xv.z * wv.x; acc[2][1] += xv.z * wv.y; acc[2][2] += xv.z * wv.z; acc[2][3] += xv.z * wv.w;
        acc[3][0] += xv.w * wv.x; acc[3][1] += xv.w * wv.y; acc[3][2] += xv.w * wv.z; acc[3][3] += xv.w * wv.w;
    }

    int e0 = tc << 2;
    int h = e0 >> 5, eo = e0 & 31;
    #pragma unroll
    for (int i = 0; i < 4; ++i) {
        int b = (tb << 2) + i;
        float4 r = make_float4(acc[i][0], acc[i][1], acc[i][2], acc[i][3]);
        *(float4*)&Out[(((h * B_ + b) * T_ + t) << 5) + eo] = r;
    }
}

// ---------------- K4: mixing coefficients ----------------
__global__ void k4_mix(const float* __restrict__ A, const float* __restrict__ L) {
    int t = blockIdx.x, s = threadIdx.x;
    float a = A[t * T_ + s], at = A[s * T_ + t];
    float lam = 1.0f / (1.0f + __expf(-L[t * T_ + s]));
    g_lamA[t * T_ + s] = lam * 0.5f * (a + at);
    g_oml[t * T_ + s] = 1.0f - lam;
}

// ---------------- K5: scores + softmax + mixing -> M (2 rows per warp) ----------------
__global__ __launch_bounds__(256) void k5_scores() {
    extern __shared__ float kT[];   // [32][513] padded transpose of K
    int hb = blockIdx.x;
    const float* K = g_k + hb * (T_ * E_);
    const float* Q = g_q + hb * (T_ * E_);
    float* M = g_M + (size_t)hb * T_ * T_;

    for (int idx = threadIdx.x; idx < T_ * E_; idx += blockDim.x) {
        int s = idx >> 5, d = idx & 31;
        kT[d * 513 + s] = K[idx];
    }
    __syncthreads();

    int warp = threadIdx.x >> 5, lane = threadIdx.x & 31;
    const float SC = 0.17677669529663687f;  // 1/sqrt(32)

    for (int ip = warp; ip < 256; ip += 8) {
        int i0 = ip << 1, i1 = i0 + 1;
        float q0 = Q[(i0 << 5) + lane];
        float q1 = Q[(i1 << 5) + lane];
        float a0[16], a1[16];
        #pragma unroll
        for (int s = 0; s < 16; ++s) { a0[s] = 0.f; a1[s] = 0.f; }
        #pragma unroll
        for (int d = 0; d < 32; ++d) {
            float qd0 = __shfl_sync(0xffffffffu, q0, d);
            float qd1 = __shfl_sync(0xffffffffu, q1, d);
            #pragma unroll
            for (int s = 0; s < 16; ++s) {
                float kk = kT[d * 513 + lane + (s << 5)];
                a0[s] += qd0 * kk;
                a1[s] += qd1 * kk;
            }
        }
        float mx0 = -1e30f, mx1 = -1e30f;
        #pragma unroll
        for (int s = 0; s < 16; ++s) {
            a0[s] *= SC; a1[s] *= SC;
            mx0 = fmaxf(mx0, a0[s]); mx1 = fmaxf(mx1, a1[s]);
        }
        #pragma unroll
        for (int o = 16; o; o >>= 1) {
            mx0 = fmaxf(mx0, __shfl_xor_sync(0xffffffffu, mx0, o));
            mx1 = fmaxf(mx1, __shfl_xor_sync(0xffffffffu, mx1, o));
        }
        float sm0 = 0.f, sm1 = 0.f;
        #pragma unroll
        for (int s = 0; s < 16; ++s) {
            a0[s] = __expf(a0[s] - mx0); sm0 += a0[s];
            a1[s] = __expf(a1[s] - mx1); sm1 += a1[s];
        }
        #pragma unroll
        for (int o = 16; o; o >>= 1) {
            sm0 += __shfl_xor_sync(0xffffffffu, sm0, o);
            sm1 += __shfl_xor_sync(0xffffffffu, sm1, o);
        }
        float in0 = 1.0f / sm0, in1 = 1.0f / sm1;
        #pragma unroll
        for (int s = 0; s < 16; ++s) {
            int j = lane + (s << 5);
            int x0 = i0 * T_ + j, x1 = i1 * T_ + j;
            M[x0] = g_lamA[x0] + g_oml[x0] * (a0[s] * in0);
            M[x1] = g_lamA[x1] + g_oml[x1] * (a1[s] * in1);
        }
    }
}

// ---------------- K6: symmetrize + exp -> EE ----------------
__global__ void k6_symexp() {
    __shared__ float sA[32][33], sB[32][33];
    int ti = blockIdx.y, tj = blockIdx.z;
    if (tj < ti) return;
    int hb = blockIdx.x;
    const float* M = g_M + (size_t)hb * T_ * T_;
    float* E = g_EE + (size_t)hb * T_ * T_;
    int tx = threadIdx.x, ty = threadIdx.y;
    sA[ty][tx] = M[(ti * 32 + ty) * T_ + tj * 32 + tx];
    sB[ty][tx] = M[(tj * 32 + ty) * T_ + ti * 32 + tx];
    __syncthreads();
    E[(ti * 32 + ty) * T_ + tj * 32 + tx] = __expf(0.5f * (sA[ty][tx] + sB[tx][ty]));
    E[(tj * 32 + ty) * T_ + ti * 32 + tx] = __expf(0.5f * (sB[ty][tx] + sA[tx][ty]));
}

// ---------------- K7: Sinkhorn, 4-CTA cluster per (h,b), fp16 tile in SMEM ----------------
// linear-domain: eu_i = 1/sum_j E_ij*ev_j ; ev_j = 1/sum_i E_ij*eu_i
// CTA r of cluster holds rows [r*128, r*128+128) as fp16 in smem.
// v-step column partials exchanged via DSMEM + barrier.cluster.
#define CBAR() do { \
    asm volatile("barrier.cluster.arrive.aligned;" ::: "memory"); \
    asm volatile("barrier.cluster.wait.aligned;"  ::: "memory"); } while (0)

__global__ __launch_bounds__(512) __cluster_dims__(4, 1, 1)
void k7_sinkhorn() {
    extern __shared__ char sm7[];
    __half2* tile = (__half2*)sm7;                     // 128 x 256 half2 (128KB)
    float* s_eu  = (float*)(sm7 + 131072);             // 128
    float* s_ev  = s_eu + 128;                         // 512
    float* pg    = s_ev + 512;                         // 1024 (2 groups x 512)
    float* slots = pg + 1024;                          // 2048 (4 ranks x 512)

    int tid = threadIdx.x;
    int hb = blockIdx.x >> 2;
    int rank = blockIdx.x & 3;
    const float* Eg = g_EE + (size_t)hb * T_ * T_ + (size_t)rank * 128 * T_;

    // load fp32 block -> fp16 smem tile
    for (int idx = tid; idx < 128 * 128; idx += 512) {
        int row = idx >> 7, c4 = idx & 127;
        float4 f = ((const float4*)(Eg + (size_t)row * T_))[c4];
        __half2 ha = __floats2half2_rn(f.x, f.y);
        __half2 hb2 = __floats2half2_rn(f.z, f.w);
        uint2 u;
        u.x = *(const unsigned int*)&ha;
        u.y = *(const unsigned int*)&hb2;
        ((uint2*)tile)[idx] = u;
    }
    s_ev[tid] = 1.0f;
    __syncthreads();
    CBAR();

    // smem u32 base for mapa
    unsigned int sbase;
    asm("{ .reg .u64 t; cvta.to.shared.u64 t, %1; cvt.u32.u64 %0, t; }"
        : "=r"(sbase) : "l"(sm7));
    unsigned int slot_off = (unsigned int)((const char*)slots - sm7);
    unsigned int my_slot_addr = sbase + slot_off + (unsigned int)(rank * 512 + tid) * 4u;

    int warp = tid >> 5, lane = tid & 31;
    int g = tid >> 8, c = tid & 255;               // v-step: group, half2-column

    for (int it = 0; it < 20; ++it) {
        // ---- u-step: local row sums with ev ----
        for (int i = warp; i < 128; i += 16) {
            const __half2* row = tile + i * 256;
            float acc = 0.f;
            #pragma unroll
            for (int m = 0; m < 8; ++m) {
                int jc = lane + (m << 5);
                float2 f = __half22float2(row[jc]);
                float2 e = *(const float2*)&s_ev[jc << 1];
                acc += f.x * e.x + f.y * e.y;
            }
            #pragma unroll
            for (int o = 16; o; o >>= 1) acc += __shfl_xor_sync(0xffffffffu, acc, o);
            if (lane == 0) s_eu[i] = 1.0f / acc;
        }
        __syncthreads();

        // ---- v-step: local column partials with eu ----
        {
            const __half2* col = tile + (g << 6) * 256 + c;
            float sx = 0.f, sy = 0.f;
            #pragma unroll 4
            for (int i = 0; i < 64; ++i) {
                float2 f = __half22float2(col[i * 256]);
                float eu = s_eu[(g << 6) + i];
                sx += f.x * eu; sy += f.y * eu;
            }
            float2 s2; s2.x = sx; s2.y = sy;
            *(float2*)&pg[(g << 9) + (c << 1)] = s2;
        }
        __syncthreads();
        float p = pg[tid] + pg[512 + tid];

        // push partial into every cluster CTA's slot[rank]
        #pragma unroll
        for (int tr = 0; tr < 4; ++tr) {
            unsigned int raddr;
            asm volatile("mapa.shared::cluster.u32 %0, %1, %2;"
                         : "=r"(raddr) : "r"(my_slot_addr), "r"(tr));
            asm volatile("st.shared::cluster.f32 [%0], %1;"
                         :: "r"(raddr), "f"(p) : "memory");
        }
        CBAR();   // writes visible
        s_ev[tid] = 1.0f / (slots[tid] + slots[512 + tid] + slots[1024 + tid] + slots[1536 + tid]);
        __syncthreads();
        CBAR();   // all reads done before next iteration's writes
    }

    if (tid < 128) g_eu[hb * T_ + rank * 128 + tid] = s_eu[tid];
    if (rank == 0) g_ev[hb * T_ + tid] = s_ev[tid];
}

// ---------------- K8: out = (E*eu*ev) @ V, 2 rows per warp ----------------
__global__ __launch_bounds__(256) void k8_out(float* __restrict__ out) {
    extern __shared__ float Ws[];   // [512][33] : V row-scaled by ev
    int hb = blockIdx.x, rb = blockIdx.y;
    int h = hb >> 4, b = hb & 15;
    const float* E = g_EE + (size_t)hb * T_ * T_;
    const float* V = g_v + hb * (T_ * E_);
    const float* ev = g_ev + hb * T_;
    const float* eu = g_eu + hb * T_;

    for (int idx = threadIdx.x; idx < T_ * E_; idx += blockDim.x) {
        int s = idx >> 5, e = idx & 31;
        Ws[s * 33 + e] = V[idx] * ev[s];
    }
    __syncthreads();

    int warp = threadIdx.x >> 5, lane = threadIdx.x & 31;
    for (int r = 0; r < 4; ++r) {
        int i0 = rb * 64 + warp * 8 + (r << 1), i1 = i0 + 1;
        float a0[32], a1[32];
        #pragma unroll
        for (int e = 0; e < 32; ++e) { a0[e] = 0.f; a1[e] = 0.f; }
        #pragma unroll 2
        for (int m = 0; m < 16; ++m) {
            int s = lane + (m << 5);
            float e0 = E[(size_t)i0 * T_ + s];
            float e1 = E[(size_t)i1 * T_ + s];
            #pragma unroll
            for (int e = 0; e < 32; ++e) {
                float w = Ws[s * 33 + e];
                a0[e] += e0 * w;
                a1[e] += e1 * w;
            }
        }
        float r0 = 0.f, r1 = 0.f;
        #pragma unroll
        for (int e = 0; e < 32; ++e) {
            float v0 = a0[e], v1 = a1[e];
            #pragma unroll
            for (int o = 16; o; o >>= 1) {
                v0 += __shfl_xor_sync(0xffffffffu, v0, o);
                v1 += __shfl_xor_sync(0xffffffffu, v1, o);
            }
            if (lane == e) { r0 = v0; r1 = v1; }
        }
        out[(((size_t)b * T_ + i0) << 8) + (h << 5) + lane] = eu[i0] * r0;
        out[(((size_t)b * T_ + i1) << 8) + (h << 5) + lane] = eu[i1] * r1;
    }
}

// ---------------- launch ----------------
extern "C" void kernel_launch(void* const* d_in, const int* in_sizes, int n_in,
                              void* d_out, int out_size) {
    const float* X  = (const float*)d_in[0];
    const float* te = (const float*)d_in[1];
    const float* Wq = (const float*)d_in[2];
    const float* Wk = (const float*)d_in[3];
    const float* Qb = (const float*)d_in[4];
    const float* Kb = (const float*)d_in[5];
    const float* WV = (const float*)d_in[6];
    const float* A  = (const float*)d_in[7];
    const float* L  = (const float*)d_in[8];
    float* out = (float*)d_out;

    const int smem5 = 32 * 513 * 4;                         // 65664
    const int smem7 = 131072 + (128 + 512 + 1024 + 2048) * 4; // 145920
    const int smem8 = 512 * 33 * 4;                         // 67584
    cudaFuncSetAttribute(k5_scores,   cudaFuncAttributeMaxDynamicSharedMemorySize, smem5);
    cudaFuncSetAttribute(k7_sinkhorn, cudaFuncAttributeMaxDynamicSharedMemorySize, smem7);
    cudaFuncSetAttribute(k8_out,      cudaFuncAttributeMaxDynamicSharedMemorySize, smem8);

    k1_weights<<<T_, 256>>>(te, Wq, Wk);
    k2_tilde<<<dim3(64, 2), 256>>>(Qb, Kb);
    k3_qkv<<<dim3(T_, 3), 256>>>(X, WV);
    k4_mix<<<T_, T_>>>(A, L);
    k5_scores<<<HB_, 256, smem5>>>();
    k6_symexp<<<dim3(HB_, 16, 16), dim3(32, 32)>>>();
    k7_sinkhorn<<<HB_ * 4, 512, smem7>>>();
    k8_out<<<dim3(HB_, 8), 256, smem8>>>(out);
}

// round 5
// speedup vs baseline: 1.6859x; 1.0613x over previous
#include <cuda_runtime.h>
#include <cuda_fp16.h>
#include <math.h>

#define B_ 16
#define T_ 512
#define D_ 256
#define H_ 8
#define E_ 32
#define BASIS_ 8
#define HB_ 128          // H_*B_
#define HE_ 256          // H_*E_

// ---------------- scratch (static device globals; no allocation) ----------------
__device__ float   g_qw[T_*BASIS_];
__device__ float   g_kw[T_*BASIS_];
__device__ __half2 g_Qt16[T_*D_*HE_/2];    // 67MB
__device__ __half2 g_Kt16[T_*D_*HE_/2];    // 67MB
__device__ float   g_q[HB_*T_*E_];         // [h][b][t][e]
__device__ float   g_k[HB_*T_*E_];
__device__ float   g_v[HB_*T_*E_];
__device__ __half2 g_lamA2[T_*256];
__device__ __half2 g_oml2[T_*256];
__device__ __half2 g_M16[(size_t)HB_*T_*256];   // 67MB mixed att (pre-symmetrization)
__device__ __half2 g_P16[(size_t)HB_*T_*256];   // 67MB final attention P = eu*E*ev

// ---------------- K1: per-token basis mixing weights ----------------
__global__ void k1_weights(const float* __restrict__ te,
                           const float* __restrict__ Wq,
                           const float* __restrict__ Wk) {
    int t = blockIdx.x;
    int warp = threadIdx.x >> 5, lane = threadIdx.x & 31;
    const float* tr = te + t * D_;
    const float* wq = Wq + (t * BASIS_ + warp) * D_;
    const float* wk = Wk + (t * BASIS_ + warp) * D_;
    float aq = 0.f, ak = 0.f;
    #pragma unroll
    for (int m = 0; m < D_ / 32; ++m) {
        int d = lane + 32 * m;
        float x = tr[d];
        aq += x * wq[d];
        ak += x * wk[d];
    }
    #pragma unroll
    for (int o = 16; o; o >>= 1) {
        aq += __shfl_xor_sync(0xffffffffu, aq, o);
        ak += __shfl_xor_sync(0xffffffffu, ak, o);
    }
    if (lane == 0) {
        g_qw[t * BASIS_ + warp] = aq;
        g_kw[t * BASIS_ + warp] = ak;
    }
}

// ---------------- K2: Q_tilde / K_tilde build (fp16 out) ----------------
__global__ void k2_tilde(const float* __restrict__ Qb, const float* __restrict__ Kb) {
    __shared__ float sW[T_ * BASIS_];
    int qk = blockIdx.y;
    const float* W = qk ? g_kw : g_qw;
    const float* Bs = qk ? Kb : Qb;
    uint2* Out = qk ? (uint2*)g_Kt16 : (uint2*)g_Qt16;
    for (int idx = threadIdx.x; idx < T_ * BASIS_; idx += blockDim.x) sW[idx] = W[idx];
    __syncthreads();

    int f4 = blockIdx.x * blockDim.x + threadIdx.x;   // float4 index, 16384 total
    float4 b4[BASIS_];
    #pragma unroll
    for (int k = 0; k < BASIS_; ++k) b4[k] = ((const float4*)Bs)[k * 16384 + f4];

    for (int t = 0; t < T_; ++t) {
        float4 a = make_float4(0.f, 0.f, 0.f, 0.f);
        #pragma unroll
        for (int k = 0; k < BASIS_; ++k) {
            float w = sW[t * BASIS_ + k];
            a.x += w * b4[k].x; a.y += w * b4[k].y;
            a.z += w * b4[k].z; a.w += w * b4[k].w;
        }
        __half2 h0 = __floats2half2_rn(a.x, a.y);
        __half2 h1 = __floats2half2_rn(a.z, a.w);
        uint2 u;
        u.x = *(const unsigned int*)&h0;
        u.y = *(const unsigned int*)&h1;
        Out[t * 16384 + f4] = u;
    }
}

// ---------------- K3a: q/k projections (fp16 weights) ----------------
__global__ __launch_bounds__(256) void k3_qk(const float* __restrict__ X) {
    __shared__ float xsT[D_][16];
    int t = blockIdx.x, m = blockIdx.y;
    const __half2* W = (m == 0 ? g_Qt16 : g_Kt16) + (size_t)t * 32768;
    float* Out = m == 0 ? g_q : g_k;

    for (int idx = threadIdx.x; idx < B_ * D_; idx += blockDim.x) {
        int b = idx >> 8, d = idx & 255;
        xsT[d][b] = X[((size_t)b * T_ + t) * D_ + d];
    }
    __syncthreads();

    int tb = threadIdx.x >> 6;   // 0..3
    int tc = threadIdx.x & 63;   // 0..63
    float acc[4][4];
    #pragma unroll
    for (int i = 0; i < 4; ++i)
        #pragma unroll
        for (int j = 0; j < 4; ++j) acc[i][j] = 0.f;

    #pragma unroll 4
    for (int d = 0; d < D_; ++d) {
        float4 xv = *(const float4*)&xsT[d][tb << 2];
        float2 f0 = __half22float2(W[d * 128 + (tc << 1)]);
        float2 f1 = __half22float2(W[d * 128 + (tc << 1) + 1]);
        acc[0][0] += xv.x * f0.x; acc[0][1] += xv.x * f0.y; acc[0][2] += xv.x * f1.x; acc[0][3] += xv.x * f1.y;
        acc[1][0] += xv.y * f0.x; acc[1][1] += xv.y * f0.y; acc[1][2] += xv.y * f1.x; acc[1][3] += xv.y * f1.y;
        acc[2][0] += xv.z * f0.x; acc[2][1] += xv.z * f0.y; acc[2][2] += xv.z * f1.x; acc[2][3] += xv.z * f1.y;
        acc[3][0] += xv.w * f0.x; acc[3][1] += xv.w * f0.y; acc[3][2] += xv.w * f1.x; acc[3][3] += xv.w * f1.y;
    }

    int e0 = tc << 2;
    int h = e0 >> 5, eo = e0 & 31;
    #pragma unroll
    for (int i = 0; i < 4; ++i) {
        int b = (tb << 2) + i;
        float4 r = make_float4(acc[i][0], acc[i][1], acc[i][2], acc[i][3]);
        *(float4*)&Out[(((h * B_ + b) * T_ + t) << 5) + eo] = r;
    }
}

// ---------------- K3b: v projection (fp32 weights from input) ----------------
__global__ __launch_bounds__(256) void k3_v(const float* __restrict__ X,
                                            const float* __restrict__ WV) {
    __shared__ float xsT[D_][16];
    int t = blockIdx.x;
    const float* W = WV + (size_t)t * 65536;

    for (int idx = threadIdx.x; idx < B_ * D_; idx += blockDim.x) {
        int b = idx >> 8, d = idx & 255;
        xsT[d][b] = X[((size_t)b * T_ + t) * D_ + d];
    }
    __syncthreads();

    int tb = threadIdx.x >> 6;
    int tc = threadIdx.x & 63;
    float acc[4][4];
    #pragma unroll
    for (int i = 0; i < 4; ++i)
        #pragma unroll
        for (int j = 0; j < 4; ++j) acc[i][j] = 0.f;

    #pragma unroll 4
    for (int d = 0; d < D_; ++d) {
        float4 xv = *(const float4*)&xsT[d][tb << 2];
        float4 wv = *(const float4*)&W[d * HE_ + (tc << 2)];
        acc[0][0] += xv.x * wv.x; acc[0][1] += xv.x * wv.y; acc[0][2] += xv.x * wv.z; acc[0][3] += xv.x * wv.w;
        acc[1][0] += xv.y * wv.x; acc[1][1] += xv.y * wv.y; acc[1][2] += xv.y * wv.z; acc[1][3] += xv.y * wv.w;
        acc[2][0] += xv.z * wv.x; acc[2][1] += xv.z * wv.y; acc[2][2] += xv.z * wv.z; acc[2][3] += xv.z * wv.w;
        acc[3][0] += xv.w * wv.x; acc[3][1] += xv.w * wv.y; acc[3][2] += xv.w * wv.z; acc[3][3] += xv.w * wv.w;
    }

    int e0 = tc << 2;
    int h = e0 >> 5, eo = e0 & 31;
    #pragma unroll
    for (int i = 0; i < 4; ++i) {
        int b = (tb << 2) + i;
        float4 r = make_float4(acc[i][0], acc[i][1], acc[i][2], acc[i][3]);
        *(float4*)&g_v[(((h * B_ + b) * T_ + t) << 5) + eo] = r;
    }
}

// ---------------- K4: mixing coefficients (half2 out) ----------------
__global__ void k4_mix(const float* __restrict__ A, const float* __restrict__ L) {
    int t = blockIdx.x, c = threadIdx.x;  // c in 0..255 (half2 col)
    int j0 = c << 1, j1 = j0 + 1;
    float a0 = 0.5f * (A[t * T_ + j0] + A[j0 * T_ + t]);
    float a1 = 0.5f * (A[t * T_ + j1] + A[j1 * T_ + t]);
    float lam0 = 1.0f / (1.0f + __expf(-L[t * T_ + j0]));
    float lam1 = 1.0f / (1.0f + __expf(-L[t * T_ + j1]));
    g_lamA2[t * 256 + c] = __floats2half2_rn(lam0 * a0, lam1 * a1);
    g_oml2[t * 256 + c]  = __floats2half2_rn(1.0f - lam0, 1.0f - lam1);
}

// ---------------- K5: scores + softmax + mixing -> M16 ----------------
__global__ __launch_bounds__(256) void k5_scores() {
    extern __shared__ float2 kT2[];   // [32][257] : kT2[d][c] = (K[2c][d], K[2c+1][d])
    int hb = blockIdx.x;
    const float* K = g_k + hb * (T_ * E_);
    const float* Q = g_q + hb * (T_ * E_);
    __half2* M = g_M16 + (size_t)hb * T_ * 256;

    for (int idx = threadIdx.x; idx < T_ * E_; idx += blockDim.x) {
        int t = idx >> 5, e = idx & 31;
        ((float*)&kT2[e * 257 + (t >> 1)])[t & 1] = K[idx];
    }
    __syncthreads();

    int warp = threadIdx.x >> 5, lane = threadIdx.x & 31;
    const float SC = 0.17677669529663687f;  // 1/sqrt(32)

    for (int ip = warp; ip < 256; ip += 8) {
        int i0 = ip << 1, i1 = i0 + 1;
        float q0 = Q[(i0 << 5) + lane];
        float q1 = Q[(i1 << 5) + lane];
        float a[8][4];
        #pragma unroll
        for (int m = 0; m < 8; ++m) { a[m][0] = a[m][1] = a[m][2] = a[m][3] = 0.f; }
        #pragma unroll
        for (int d = 0; d < 32; ++d) {
            float qd0 = __shfl_sync(0xffffffffu, q0, d);
            float qd1 = __shfl_sync(0xffffffffu, q1, d);
            const float2* row = &kT2[d * 257];
            #pragma unroll
            for (int m = 0; m < 8; ++m) {
                float2 kv = row[lane + (m << 5)];
                a[m][0] += qd0 * kv.x; a[m][1] += qd0 * kv.y;
                a[m][2] += qd1 * kv.x; a[m][3] += qd1 * kv.y;
            }
        }
        float mx0 = -1e30f, mx1 = -1e30f;
        #pragma unroll
        for (int m = 0; m < 8; ++m) {
            a[m][0] *= SC; a[m][1] *= SC; a[m][2] *= SC; a[m][3] *= SC;
            mx0 = fmaxf(mx0, fmaxf(a[m][0], a[m][1]));
            mx1 = fmaxf(mx1, fmaxf(a[m][2], a[m][3]));
        }
        #pragma unroll
        for (int o = 16; o; o >>= 1) {
            mx0 = fmaxf(mx0, __shfl_xor_sync(0xffffffffu, mx0, o));
            mx1 = fmaxf(mx1, __shfl_xor_sync(0xffffffffu, mx1, o));
        }
        float sm0 = 0.f, sm1 = 0.f;
        #pragma unroll
        for (int m = 0; m < 8; ++m) {
            a[m][0] = __expf(a[m][0] - mx0); a[m][1] = __expf(a[m][1] - mx0);
            a[m][2] = __expf(a[m][2] - mx1); a[m][3] = __expf(a[m][3] - mx1);
            sm0 += a[m][0] + a[m][1];
            sm1 += a[m][2] + a[m][3];
        }
        #pragma unroll
        for (int o = 16; o; o >>= 1) {
            sm0 += __shfl_xor_sync(0xffffffffu, sm0, o);
            sm1 += __shfl_xor_sync(0xffffffffu, sm1, o);
        }
        float in0 = 1.0f / sm0, in1 = 1.0f / sm1;
        #pragma unroll
        for (int m = 0; m < 8; ++m) {
            int c = lane + (m << 5);
            float2 la0 = __half22float2(g_lamA2[i0 * 256 + c]);
            float2 om0 = __half22float2(g_oml2[i0 * 256 + c]);
            float2 la1 = __half22float2(g_lamA2[i1 * 256 + c]);
            float2 om1 = __half22float2(g_oml2[i1 * 256 + c]);
            M[(size_t)i0 * 256 + c] = __floats2half2_rn(la0.x + om0.x * (a[m][0] * in0),
                                                        la0.y + om0.y * (a[m][1] * in0));
            M[(size_t)i1 * 256 + c] = __floats2half2_rn(la1.x + om1.x * (a[m][2] * in1),
                                                        la1.y + om1.y * (a[m][3] * in1));
        }
    }
}

// ---------------- K7: fused symexp + Sinkhorn + final scaling -> P16 ----------------
// CTA rank r of 4-CTA cluster holds rows [128r,128r+128) as fp16 in smem.
// tile[i][j] = exp(0.5*(M[i,j]+M[j,i])); 20 iters; P = eu*tile*ev written fp16.
#define CBAR() do { \
    asm volatile("barrier.cluster.arrive.aligned;" ::: "memory"); \
    asm volatile("barrier.cluster.wait.aligned;"  ::: "memory"); } while (0)

__global__ __launch_bounds__(512) __cluster_dims__(4, 1, 1)
void k7_sinkhorn() {
    extern __shared__ char sm7[];
    __half2* tile  = (__half2*)sm7;                      // 128 x 256 half2  (131072 B)
    __half*  stage = (__half*)(sm7 + 131072);            // 128 x 130 half   (33280 B)
    float* s_eu = (float*)(sm7 + 164352);                // 128
    float* s_ev = s_eu + 128;                            // 512
    float* pg   = s_ev + 512;                            // 1024
    float* slots = pg + 1024;                            // 2 x 4 x 512 floats (double buffered)

    int tid = threadIdx.x;
    int hb = blockIdx.x >> 2;
    int rank = blockIdx.x & 3;
    const __half2* Mg = g_M16 + (size_t)hb * T_ * 256;

    // ---- fused symmetrize + exp load: 4 sub-blocks of 128x128 ----
    #pragma unroll 1
    for (int s = 0; s < 4; ++s) {
        for (int idx = tid; idx < 128 * 64; idx += 512) {
            int j = idx >> 6, c2 = idx & 63;
            __half2 v = Mg[(size_t)(128 * s + j) * 256 + rank * 64 + c2];
            *(__half2*)&stage[j * 130 + (c2 << 1)] = v;
        }
        __syncthreads();
        for (int idx = tid; idx < 128 * 64; idx += 512) {
            int i = idx >> 6, c2 = idx & 63;
            float2 fa = __half22float2(Mg[(size_t)(128 * rank + i) * 256 + (s << 6) + c2]);
            float b0 = __half2float(stage[(c2 << 1) * 130 + i]);
            float b1 = __half2float(stage[((c2 << 1) + 1) * 130 + i]);
            float e0 = __expf(0.5f * (fa.x + b0));
            float e1 = __expf(0.5f * (fa.y + b1));
            tile[i * 256 + (s << 6) + c2] = __floats2half2_rn(e0, e1);
        }
        __syncthreads();
    }
    s_ev[tid] = 1.0f;
    __syncthreads();
    CBAR();

    unsigned int sbase;
    asm("{ .reg .u64 t; cvta.to.shared.u64 t, %1; cvt.u32.u64 %0, t; }"
        : "=r"(sbase) : "l"(sm7));
    const unsigned int slots_off = 164352u + (128u + 512u + 1024u) * 4u;  // 171008

    int warp = tid >> 5, lane = tid & 31;
    int g = tid >> 8, c = tid & 255;
    int buf = 0;

    for (int it = 0; it < 20; ++it) {
        // ---- u-step: row sums with ev ----
        for (int i = warp; i < 128; i += 16) {
            const __half2* row = tile + i * 256;
            float acc = 0.f;
            #pragma unroll
            for (int m = 0; m < 8; ++m) {
                int jc = lane + (m << 5);
                float2 f = __half22float2(row[jc]);
                float2 e = *(const float2*)&s_ev[jc << 1];
                acc += f.x * e.x + f.y * e.y;
            }
            #pragma unroll
            for (int o = 16; o; o >>= 1) acc += __shfl_xor_sync(0xffffffffu, acc, o);
            if (lane == 0) s_eu[i] = 1.0f / acc;
        }
        __syncthreads();

        // ---- v-step: column partials with eu ----
        {
            const __half2* col = tile + (g << 6) * 256 + c;
            float sx = 0.f, sy = 0.f;
            #pragma unroll 4
            for (int i = 0; i < 64; ++i) {
                float2 f = __half22float2(col[i * 256]);
                float eu = s_eu[(g << 6) + i];
                sx += f.x * eu; sy += f.y * eu;
            }
            float2 s2; s2.x = sx; s2.y = sy;
            *(float2*)&pg[(g << 9) + (c << 1)] = s2;
        }
        __syncthreads();
        float p = pg[tid] + pg[512 + tid];

        unsigned int my_addr = sbase + slots_off + (unsigned)buf * 8192u
                             + (unsigned)(rank * 512 + tid) * 4u;
        #pragma unroll
        for (int tr = 0; tr < 4; ++tr) {
            unsigned int raddr;
            asm volatile("mapa.shared::cluster.u32 %0, %1, %2;"
                         : "=r"(raddr) : "r"(my_addr), "r"(tr));
            asm volatile("st.shared::cluster.f32 [%0], %1;"
                         :: "r"(raddr), "f"(p) : "memory");
        }
        CBAR();
        const float* sl = slots + buf * 2048;
        s_ev[tid] = 1.0f / (sl[tid] + sl[512 + tid] + sl[1024 + tid] + sl[1536 + tid]);
        __syncthreads();
        buf ^= 1;
    }

    // ---- write P16 = eu * tile * ev ----
    __half2* Pg = g_P16 + (size_t)hb * T_ * 256 + (size_t)(128 * rank) * 256;
    for (int idx = tid; idx < 128 * 256; idx += 512) {
        int i = idx >> 8, cc = idx & 255;
        float2 f = __half22float2(tile[idx]);
        float si = s_eu[i];
        f.x *= si * s_ev[cc << 1];
        f.y *= si * s_ev[(cc << 1) + 1];
        Pg[idx] = __floats2half2_rn(f.x, f.y);
    }
}

// ---------------- K8: out = P16 @ V ----------------
__global__ __launch_bounds__(256) void k8_out(float* __restrict__ out) {
    extern __shared__ float Ws[];   // Ws0[256*33] even rows of V, Ws1[256*33] odd rows
    float* Ws0 = Ws;
    float* Ws1 = Ws + 256 * 33;
    int hb = blockIdx.x, rb = blockIdx.y;
    int h = hb >> 4, b = hb & 15;
    const __half2* P = g_P16 + (size_t)hb * T_ * 256;
    const float* V = g_v + hb * (T_ * E_);

    for (int idx = threadIdx.x; idx < T_ * E_; idx += blockDim.x) {
        int s = idx >> 5, e = idx & 31;
        float v = V[idx];
        if (s & 1) Ws1[(s >> 1) * 33 + e] = v;
        else       Ws0[(s >> 1) * 33 + e] = v;
    }
    __syncthreads();

    int warp = threadIdx.x >> 5, lane = threadIdx.x & 31;
    for (int r = 0; r < 4; ++r) {
        int i0 = rb * 64 + warp * 8 + (r << 1), i1 = i0 + 1;
        float a0[32], a1[32];
        #pragma unroll
        for (int e = 0; e < 32; ++e) { a0[e] = 0.f; a1[e] = 0.f; }
        #pragma unroll
        for (int m = 0; m < 8; ++m) {
            int c = lane + (m << 5);
            float2 p0 = __half22float2(P[(size_t)i0 * 256 + c]);
            float2 p1 = __half22float2(P[(size_t)i1 * 256 + c]);
            #pragma unroll
            for (int e = 0; e < 32; ++e) {
                float w0 = Ws0[c * 33 + e];
                float w1 = Ws1[c * 33 + e];
                a0[e] += p0.x * w0 + p0.y * w1;
                a1[e] += p1.x * w0 + p1.y * w1;
            }
        }
        float r0 = 0.f, r1 = 0.f;
        #pragma unroll
        for (int e = 0; e < 32; ++e) {
            float v0 = a0[e], v1 = a1[e];
            #pragma unroll
            for (int o = 16; o; o >>= 1) {
                v0 += __shfl_xor_sync(0xffffffffu, v0, o);
                v1 += __shfl_xor_sync(0xffffffffu, v1, o);
            }
            if (lane == e) { r0 = v0; r1 = v1; }
        }
        out[(((size_t)b * T_ + i0) << 8) + (h << 5) + lane] = r0;
        out[(((size_t)b * T_ + i1) << 8) + (h << 5) + lane] = r1;
    }
}

// ---------------- launch ----------------
extern "C" void kernel_launch(void* const* d_in, const int* in_sizes, int n_in,
                              void* d_out, int out_size) {
    const float* X  = (const float*)d_in[0];
    const float* te = (const float*)d_in[1];
    const float* Wq = (const float*)d_in[2];
    const float* Wk = (const float*)d_in[3];
    const float* Qb = (const float*)d_in[4];
    const float* Kb = (const float*)d_in[5];
    const float* WV = (const float*)d_in[6];
    const float* A  = (const float*)d_in[7];
    const float* L  = (const float*)d_in[8];
    float* out = (float*)d_out;

    const int smem5 = 32 * 257 * 8;                 // 65792
    const int smem7 = 164352 + (128 + 512 + 1024 + 4096) * 4;  // 187392
    const int smem8 = 2 * 256 * 33 * 4;             // 67584
    cudaFuncSetAttribute(k5_scores,   cudaFuncAttributeMaxDynamicSharedMemorySize, smem5);
    cudaFuncSetAttribute(k7_sinkhorn, cudaFuncAttributeMaxDynamicSharedMemorySize, smem7);
    cudaFuncSetAttribute(k8_out,      cudaFuncAttributeMaxDynamicSharedMemorySize, smem8);

    k1_weights<<<T_, 256>>>(te, Wq, Wk);
    k2_tilde<<<dim3(64, 2), 256>>>(Qb, Kb);
    k3_qk<<<dim3(T_, 2), 256>>>(X);
    k3_v<<<T_, 256>>>(X, WV);
    k4_mix<<<T_, 256>>>(A, L);
    k5_scores<<<HB_, 256, smem5>>>();
    k7_sinkhorn<<<HB_ * 4, 512, smem7>>>();
    k8_out<<<dim3(HB_, 8), 256, smem8>>>(out);
}

// round 6
// speedup vs baseline: 2.1231x; 1.2594x over previous
#include <cuda_runtime.h>
#include <cuda_fp16.h>
#include <math.h>

#define B_ 16
#define T_ 512
#define D_ 256
#define H_ 8
#define E_ 32
#define BASIS_ 8
#define HB_ 128          // H_*B_
#define HE_ 256          // H_*E_

// ---------------- scratch (static device globals; no allocation) ----------------
__device__ float   g_qw[T_*BASIS_];
__device__ float   g_kw[T_*BASIS_];
__device__ __half2 g_Qt16[T_*D_*HE_/2];    // 67MB
__device__ __half2 g_Kt16[T_*D_*HE_/2];    // 67MB
__device__ float   g_q[HB_*T_*E_];         // [h][b][t][e]
__device__ float   g_k[HB_*T_*E_];
__device__ float   g_v[HB_*T_*E_];
__device__ __half2 g_lamA2[T_*256];
__device__ __half2 g_oml2[T_*256];
__device__ __half2 g_M16[(size_t)HB_*T_*256];   // 67MB mixed att (pre-symmetrization)
__device__ __half2 g_P16[(size_t)HB_*T_*256];   // 67MB final attention P = eu*E*ev

// ---------------- K1: per-token basis mixing weights ----------------
__global__ void k1_weights(const float* __restrict__ te,
                           const float* __restrict__ Wq,
                           const float* __restrict__ Wk) {
    int t = blockIdx.x;
    int warp = threadIdx.x >> 5, lane = threadIdx.x & 31;
    const float* tr = te + t * D_;
    const float* wq = Wq + (t * BASIS_ + warp) * D_;
    const float* wk = Wk + (t * BASIS_ + warp) * D_;
    float aq = 0.f, ak = 0.f;
    #pragma unroll
    for (int m = 0; m < D_ / 32; ++m) {
        int d = lane + 32 * m;
        float x = tr[d];
        aq += x * wq[d];
        ak += x * wk[d];
    }
    #pragma unroll
    for (int o = 16; o; o >>= 1) {
        aq += __shfl_xor_sync(0xffffffffu, aq, o);
        ak += __shfl_xor_sync(0xffffffffu, ak, o);
    }
    if (lane == 0) {
        g_qw[t * BASIS_ + warp] = aq;
        g_kw[t * BASIS_ + warp] = ak;
    }
}

// ---------------- K2: Q_tilde / K_tilde build (fp16 out), t-chunked ----------------
__global__ __launch_bounds__(256) void k2_tilde(const float* __restrict__ Qb,
                                                const float* __restrict__ Kb) {
    __shared__ float sW[64 * BASIS_];
    int qk = blockIdx.y;
    int t0 = blockIdx.z << 6;          // 64-token chunk
    const float* W = (qk ? g_kw : g_qw) + t0 * BASIS_;
    const float* Bs = qk ? Kb : Qb;
    uint2* Out = qk ? (uint2*)g_Kt16 : (uint2*)g_Qt16;
    for (int idx = threadIdx.x; idx < 64 * BASIS_; idx += 256) sW[idx] = W[idx];
    __syncthreads();

    int f4 = blockIdx.x * 256 + threadIdx.x;   // float4 index, 16384 total
    float4 b4[BASIS_];
    #pragma unroll
    for (int k = 0; k < BASIS_; ++k) b4[k] = ((const float4*)Bs)[k * 16384 + f4];

    for (int tt = 0; tt < 64; ++tt) {
        float4 a = make_float4(0.f, 0.f, 0.f, 0.f);
        #pragma unroll
        for (int k = 0; k < BASIS_; ++k) {
            float w = sW[tt * BASIS_ + k];
            a.x += w * b4[k].x; a.y += w * b4[k].y;
            a.z += w * b4[k].z; a.w += w * b4[k].w;
        }
        __half2 h0 = __floats2half2_rn(a.x, a.y);
        __half2 h1 = __floats2half2_rn(a.z, a.w);
        uint2 u;
        u.x = *(const unsigned int*)&h0;
        u.y = *(const unsigned int*)&h1;
        Out[(t0 + tt) * 16384 + f4] = u;
    }
}

// ---------------- K3: all q/k/v projections, one launch ----------------
// per (t, m): [16,256] @ [256,256] -> scatter to [h][b][t][e]
// thread tile: 2 b-rows x 8 cols; fp16 W row chunk = single LDG.128
__global__ __launch_bounds__(256) void k3_qkv(const float* __restrict__ X,
                                              const float* __restrict__ WV) {
    __shared__ float xsT[D_][16];
    int t = blockIdx.x, m = blockIdx.y;

    for (int idx = threadIdx.x; idx < B_ * D_; idx += 256) {
        int b = idx >> 8, d = idx & 255;
        xsT[d][b] = X[((size_t)b * T_ + t) * D_ + d];
    }
    __syncthreads();

    int tc = threadIdx.x & 31;   // col group: cols [8tc, 8tc+8)
    int tb = threadIdx.x >> 5;   // b pair: 2tb, 2tb+1
    float acc[2][8];
    #pragma unroll
    for (int i = 0; i < 2; ++i)
        #pragma unroll
        for (int j = 0; j < 8; ++j) acc[i][j] = 0.f;

    if (m < 2) {
        const uint4* W = (const uint4*)((m == 0 ? g_Qt16 : g_Kt16) + (size_t)t * 32768);
        #pragma unroll 8
        for (int d = 0; d < D_; ++d) {
            float2 xv = *(const float2*)&xsT[d][tb << 1];
            uint4 wr = W[(d << 5) + tc];          // 4 half2 = cols 8tc..8tc+7
            float2 w0 = __half22float2(*(const __half2*)&wr.x);
            float2 w1 = __half22float2(*(const __half2*)&wr.y);
            float2 w2 = __half22float2(*(const __half2*)&wr.z);
            float2 w3 = __half22float2(*(const __half2*)&wr.w);
            acc[0][0] += xv.x * w0.x; acc[0][1] += xv.x * w0.y;
            acc[0][2] += xv.x * w1.x; acc[0][3] += xv.x * w1.y;
            acc[0][4] += xv.x * w2.x; acc[0][5] += xv.x * w2.y;
            acc[0][6] += xv.x * w3.x; acc[0][7] += xv.x * w3.y;
            acc[1][0] += xv.y * w0.x; acc[1][1] += xv.y * w0.y;
            acc[1][2] += xv.y * w1.x; acc[1][3] += xv.y * w1.y;
            acc[1][4] += xv.y * w2.x; acc[1][5] += xv.y * w2.y;
            acc[1][6] += xv.y * w3.x; acc[1][7] += xv.y * w3.y;
        }
    } else {
        const float* W = WV + (size_t)t * 65536;
        #pragma unroll 4
        for (int d = 0; d < D_; ++d) {
            float2 xv = *(const float2*)&xsT[d][tb << 1];
            float4 wa = *(const float4*)&W[(d << 8) + (tc << 3)];
            float4 wb = *(const float4*)&W[(d << 8) + (tc << 3) + 4];
            acc[0][0] += xv.x * wa.x; acc[0][1] += xv.x * wa.y;
            acc[0][2] += xv.x * wa.z; acc[0][3] += xv.x * wa.w;
            acc[0][4] += xv.x * wb.x; acc[0][5] += xv.x * wb.y;
            acc[0][6] += xv.x * wb.z; acc[0][7] += xv.x * wb.w;
            acc[1][0] += xv.y * wa.x; acc[1][1] += xv.y * wa.y;
            acc[1][2] += xv.y * wa.z; acc[1][3] += xv.y * wa.w;
            acc[1][4] += xv.y * wb.x; acc[1][5] += xv.y * wb.y;
            acc[1][6] += xv.y * wb.z; acc[1][7] += xv.y * wb.w;
        }
    }

    float* Out = (m == 0) ? g_q : (m == 1) ? g_k : g_v;
    int e0 = tc << 3;
    int h = e0 >> 5, eo = e0 & 31;
    #pragma unroll
    for (int i = 0; i < 2; ++i) {
        int b = (tb << 1) + i;
        size_t base = (((size_t)(h * B_ + b) * T_ + t) << 5) + eo;
        *(float4*)&Out[base]     = make_float4(acc[i][0], acc[i][1], acc[i][2], acc[i][3]);
        *(float4*)&Out[base + 4] = make_float4(acc[i][4], acc[i][5], acc[i][6], acc[i][7]);
    }
}

// ---------------- K4: mixing coefficients (half2 out) ----------------
__global__ void k4_mix(const float* __restrict__ A, const float* __restrict__ L) {
    int t = blockIdx.x, c = threadIdx.x;  // c in 0..255 (half2 col)
    int j0 = c << 1, j1 = j0 + 1;
    float a0 = 0.5f * (A[t * T_ + j0] + A[j0 * T_ + t]);
    float a1 = 0.5f * (A[t * T_ + j1] + A[j1 * T_ + t]);
    float lam0 = 1.0f / (1.0f + __expf(-L[t * T_ + j0]));
    float lam1 = 1.0f / (1.0f + __expf(-L[t * T_ + j1]));
    g_lamA2[t * 256 + c] = __floats2half2_rn(lam0 * a0, lam1 * a1);
    g_oml2[t * 256 + c]  = __floats2half2_rn(1.0f - lam0, 1.0f - lam1);
}

// ---------------- K5: scores + softmax + mixing -> M16 ----------------
__global__ __launch_bounds__(256) void k5_scores() {
    extern __shared__ float2 kT2[];   // [32][257] : kT2[d][c] = (K[2c][d], K[2c+1][d])
    int hb = blockIdx.x;
    const float* K = g_k + hb * (T_ * E_);
    const float* Q = g_q + hb * (T_ * E_);
    __half2* M = g_M16 + (size_t)hb * T_ * 256;

    for (int idx = threadIdx.x; idx < T_ * E_; idx += blockDim.x) {
        int t = idx >> 5, e = idx & 31;
        ((float*)&kT2[e * 257 + (t >> 1)])[t & 1] = K[idx];
    }
    __syncthreads();

    int warp = threadIdx.x >> 5, lane = threadIdx.x & 31;
    const float SC = 0.17677669529663687f;  // 1/sqrt(32)

    for (int ip = warp; ip < 256; ip += 8) {
        int i0 = ip << 1, i1 = i0 + 1;
        float q0 = Q[(i0 << 5) + lane];
        float q1 = Q[(i1 << 5) + lane];
        float a[8][4];
        #pragma unroll
        for (int m = 0; m < 8; ++m) { a[m][0] = a[m][1] = a[m][2] = a[m][3] = 0.f; }
        #pragma unroll
        for (int d = 0; d < 32; ++d) {
            float qd0 = __shfl_sync(0xffffffffu, q0, d);
            float qd1 = __shfl_sync(0xffffffffu, q1, d);
            const float2* row = &kT2[d * 257];
            #pragma unroll
            for (int m = 0; m < 8; ++m) {
                float2 kv = row[lane + (m << 5)];
                a[m][0] += qd0 * kv.x; a[m][1] += qd0 * kv.y;
                a[m][2] += qd1 * kv.x; a[m][3] += qd1 * kv.y;
            }
        }
        float mx0 = -1e30f, mx1 = -1e30f;
        #pragma unroll
        for (int m = 0; m < 8; ++m) {
            a[m][0] *= SC; a[m][1] *= SC; a[m][2] *= SC; a[m][3] *= SC;
            mx0 = fmaxf(mx0, fmaxf(a[m][0], a[m][1]));
            mx1 = fmaxf(mx1, fmaxf(a[m][2], a[m][3]));
        }
        #pragma unroll
        for (int o = 16; o; o >>= 1) {
            mx0 = fmaxf(mx0, __shfl_xor_sync(0xffffffffu, mx0, o));
            mx1 = fmaxf(mx1, __shfl_xor_sync(0xffffffffu, mx1, o));
        }
        float sm0 = 0.f, sm1 = 0.f;
        #pragma unroll
        for (int m = 0; m < 8; ++m) {
            a[m][0] = __expf(a[m][0] - mx0); a[m][1] = __expf(a[m][1] - mx0);
            a[m][2] = __expf(a[m][2] - mx1); a[m][3] = __expf(a[m][3] - mx1);
            sm0 += a[m][0] + a[m][1];
            sm1 += a[m][2] + a[m][3];
        }
        #pragma unroll
        for (int o = 16; o; o >>= 1) {
            sm0 += __shfl_xor_sync(0xffffffffu, sm0, o);
            sm1 += __shfl_xor_sync(0xffffffffu, sm1, o);
        }
        float in0 = 1.0f / sm0, in1 = 1.0f / sm1;
        #pragma unroll
        for (int m = 0; m < 8; ++m) {
            int c = lane + (m << 5);
            float2 la0 = __half22float2(g_lamA2[i0 * 256 + c]);
            float2 om0 = __half22float2(g_oml2[i0 * 256 + c]);
            float2 la1 = __half22float2(g_lamA2[i1 * 256 + c]);
            float2 om1 = __half22float2(g_oml2[i1 * 256 + c]);
            M[(size_t)i0 * 256 + c] = __floats2half2_rn(la0.x + om0.x * (a[m][0] * in0),
                                                        la0.y + om0.y * (a[m][1] * in0));
            M[(size_t)i1 * 256 + c] = __floats2half2_rn(la1.x + om1.x * (a[m][2] * in1),
                                                        la1.y + om1.y * (a[m][3] * in1));
        }
    }
}

// ---------------- K7: fused symexp + Sinkhorn + final scaling -> P16 ----------------
#define CBAR() do { \
    asm volatile("barrier.cluster.arrive.aligned;" ::: "memory"); \
    asm volatile("barrier.cluster.wait.aligned;"  ::: "memory"); } while (0)

__global__ __launch_bounds__(512) __cluster_dims__(4, 1, 1)
void k7_sinkhorn() {
    extern __shared__ char sm7[];
    __half2* tile  = (__half2*)sm7;                      // 128 x 256 half2  (131072 B)
    __half*  stage = (__half*)(sm7 + 131072);            // 128 x 130 half   (33280 B)
    float* s_eu = (float*)(sm7 + 164352);                // 128
    float* s_ev = s_eu + 128;                            // 512
    float* pg   = s_ev + 512;                            // 1024
    float* slots = pg + 1024;                            // 2 x 4 x 512 floats (double buffered)

    int tid = threadIdx.x;
    int hb = blockIdx.x >> 2;
    int rank = blockIdx.x & 3;
    const __half2* Mg = g_M16 + (size_t)hb * T_ * 256;

    // ---- fused symmetrize + exp load: 4 sub-blocks of 128x128 ----
    #pragma unroll 1
    for (int s = 0; s < 4; ++s) {
        for (int idx = tid; idx < 128 * 64; idx += 512) {
            int j = idx >> 6, c2 = idx & 63;
            __half2 v = Mg[(size_t)(128 * s + j) * 256 + rank * 64 + c2];
            *(__half2*)&stage[j * 130 + (c2 << 1)] = v;
        }
        __syncthreads();
        for (int idx = tid; idx < 128 * 64; idx += 512) {
            int i = idx >> 6, c2 = idx & 63;
            float2 fa = __half22float2(Mg[(size_t)(128 * rank + i) * 256 + (s << 6) + c2]);
            float b0 = __half2float(stage[(c2 << 1) * 130 + i]);
            float b1 = __half2float(stage[((c2 << 1) + 1) * 130 + i]);
            float e0 = __expf(0.5f * (fa.x + b0));
            float e1 = __expf(0.5f * (fa.y + b1));
            tile[i * 256 + (s << 6) + c2] = __floats2half2_rn(e0, e1);
        }
        __syncthreads();
    }
    s_ev[tid] = 1.0f;
    __syncthreads();
    CBAR();

    unsigned int sbase;
    asm("{ .reg .u64 t; cvta.to.shared.u64 t, %1; cvt.u32.u64 %0, t; }"
        : "=r"(sbase) : "l"(sm7));
    const unsigned int slots_off = 164352u + (128u + 512u + 1024u) * 4u;  // 171008

    int warp = tid >> 5, lane = tid & 31;
    int g = tid >> 8, c = tid & 255;
    int buf = 0;

    for (int it = 0; it < 20; ++it) {
        // ---- u-step: row sums with ev ----
        for (int i = warp; i < 128; i += 16) {
            const __half2* row = tile + i * 256;
            float acc = 0.f;
            #pragma unroll
            for (int m = 0; m < 8; ++m) {
                int jc = lane + (m << 5);
                float2 f = __half22float2(row[jc]);
                float2 e = *(const float2*)&s_ev[jc << 1];
                acc += f.x * e.x + f.y * e.y;
            }
            #pragma unroll
            for (int o = 16; o; o >>= 1) acc += __shfl_xor_sync(0xffffffffu, acc, o);
            if (lane == 0) s_eu[i] = 1.0f / acc;
        }
        __syncthreads();

        // ---- v-step: column partials with eu ----
        {
            const __half2* col = tile + (g << 6) * 256 + c;
            float sx = 0.f, sy = 0.f;
            #pragma unroll 4
            for (int i = 0; i < 64; ++i) {
                float2 f = __half22float2(col[i * 256]);
                float eu = s_eu[(g << 6) + i];
                sx += f.x * eu; sy += f.y * eu;
            }
            float2 s2; s2.x = sx; s2.y = sy;
            *(float2*)&pg[(g << 9) + (c << 1)] = s2;
        }
        __syncthreads();
        float p = pg[tid] + pg[512 + tid];

        unsigned int my_addr = sbase + slots_off + (unsigned)buf * 8192u
                             + (unsigned)(rank * 512 + tid) * 4u;
        #pragma unroll
        for (int tr = 0; tr < 4; ++tr) {
            unsigned int raddr;
            asm volatile("mapa.shared::cluster.u32 %0, %1, %2;"
                         : "=r"(raddr) : "r"(my_addr), "r"(tr));
            asm volatile("st.shared::cluster.f32 [%0], %1;"
                         :: "r"(raddr), "f"(p) : "memory");
        }
        CBAR();
        const float* sl = slots + buf * 2048;
        s_ev[tid] = 1.0f / (sl[tid] + sl[512 + tid] + sl[1024 + tid] + sl[1536 + tid]);
        __syncthreads();
        buf ^= 1;
    }

    // ---- write P16 = eu * tile * ev ----
    __half2* Pg = g_P16 + (size_t)hb * T_ * 256 + (size_t)(128 * rank) * 256;
    for (int idx = tid; idx < 128 * 256; idx += 512) {
        int i = idx >> 8, cc = idx & 255;
        float2 f = __half22float2(tile[idx]);
        float si = s_eu[i];
        f.x *= si * s_ev[cc << 1];
        f.y *= si * s_ev[(cc << 1) + 1];
        Pg[idx] = __floats2half2_rn(f.x, f.y);
    }
}

// ---------------- K8: out = P16 @ V, outer-product smem GEMM ----------------
__global__ __launch_bounds__(256) void k8_out(float* __restrict__ out) {
    extern __shared__ char s8[];
    __half2* Ps = (__half2*)s8;            // 64 rows x 256 half2 = 64KB
    float*   Vs = (float*)(s8 + 65536);    // 512 x 32 f32 = 64KB
    int hb = blockIdx.x, rb = blockIdx.y;
    int h = hb >> 4, b = hb & 15;
    const __half2* P = g_P16 + (size_t)hb * T_ * 256 + (size_t)rb * 64 * 256;
    const float* V = g_v + hb * (T_ * E_);

    for (int idx = threadIdx.x; idx < 64 * 256; idx += 256)
        Ps[idx] = P[idx];
    for (int idx = threadIdx.x; idx < 512 * 32; idx += 256)
        Vs[idx] = V[idx];
    __syncthreads();

    int warp = threadIdx.x >> 5, lane = threadIdx.x & 31;
    float acc[8];
    #pragma unroll
    for (int r = 0; r < 8; ++r) acc[r] = 0.f;

    // s processed 4 at a time (2 half2 per row via LDS.64)
    #pragma unroll 2
    for (int s4 = 0; s4 < 128; ++s4) {
        int s0 = s4 << 2;
        float v0 = Vs[(s0 + 0) * 32 + lane];
        float v1 = Vs[(s0 + 1) * 32 + lane];
        float v2 = Vs[(s0 + 2) * 32 + lane];
        float v3 = Vs[(s0 + 3) * 32 + lane];
        #pragma unroll
        for (int r = 0; r < 8; ++r) {
            uint2 pr = *(const uint2*)&Ps[(warp * 8 + r) * 256 + (s4 << 1)];
            float2 pa = __half22float2(*(const __half2*)&pr.x);
            float2 pb = __half22float2(*(const __half2*)&pr.y);
            acc[r] += pa.x * v0 + pa.y * v1 + pb.x * v2 + pb.y * v3;
        }
    }

    #pragma unroll
    for (int r = 0; r < 8; ++r) {
        int i = rb * 64 + warp * 8 + r;
        out[(((size_t)b * T_ + i) << 8) + (h << 5) + lane] = acc[r];
    }
}

// ---------------- launch ----------------
extern "C" void kernel_launch(void* const* d_in, const int* in_sizes, int n_in,
                              void* d_out, int out_size) {
    const float* X  = (const float*)d_in[0];
    const float* te = (const float*)d_in[1];
    const float* Wq = (const float*)d_in[2];
    const float* Wk = (const float*)d_in[3];
    const float* Qb = (const float*)d_in[4];
    const float* Kb = (const float*)d_in[5];
    const float* WV = (const float*)d_in[6];
    const float* A  = (const float*)d_in[7];
    const float* L  = (const float*)d_in[8];
    float* out = (float*)d_out;

    const int smem5 = 32 * 257 * 8;                             // 65792
    const int smem7 = 164352 + (128 + 512 + 1024 + 4096) * 4;   // 187392
    const int smem8 = 65536 + 65536;                            // 131072
    cudaFuncSetAttribute(k5_scores,   cudaFuncAttributeMaxDynamicSharedMemorySize, smem5);
    cudaFuncSetAttribute(k7_sinkhorn, cudaFuncAttributeMaxDynamicSharedMemorySize, smem7);
    cudaFuncSetAttribute(k8_out,      cudaFuncAttributeMaxDynamicSharedMemorySize, smem8);

    k1_weights<<<T_, 256>>>(te, Wq, Wk);
    k2_tilde<<<dim3(64, 2, 8), 256>>>(Qb, Kb);
    k3_qkv<<<dim3(T_, 3), 256>>>(X, WV);
    k4_mix<<<T_, 256>>>(A, L);
    k5_scores<<<HB_, 256, smem5>>>();
    k7_sinkhorn<<<HB_ * 4, 512, smem7>>>();
    k8_out<<<dim3(HB_, 8), 256, smem8>>>(out);
}

// round 7
// speedup vs baseline: 2.3683x; 1.1155x over previous
#include <cuda_runtime.h>
#include <cuda_fp16.h>
#include <math.h>

#define B_ 16
#define T_ 512
#define D_ 256
#define H_ 8
#define E_ 32
#define BASIS_ 8
#define HB_ 128          // H_*B_
#define HE_ 256          // H_*E_

// ---------------- scratch (static device globals; no allocation) ----------------
__device__ float   g_qw[T_*BASIS_];
__device__ float   g_kw[T_*BASIS_];
__device__ __half2 g_Qt16[T_*D_*HE_/2];    // 67MB
__device__ __half2 g_Kt16[T_*D_*HE_/2];    // 67MB
__device__ float   g_q[HB_*T_*E_];         // [h][b][t][e] fp32
__device__ float   g_k[HB_*T_*E_];
__device__ __half2 g_v16[HB_*T_*E_/2];     // [h][b][t][e] fp16 (4MB)
__device__ __half2 g_lamA2[T_*256];
__device__ __half2 g_oml2[T_*256];

// ---------------- K1: per-token basis mixing weights ----------------
__global__ void k1_weights(const float* __restrict__ te,
                           const float* __restrict__ Wq,
                           const float* __restrict__ Wk) {
    int t = blockIdx.x;
    int warp = threadIdx.x >> 5, lane = threadIdx.x & 31;
    const float* tr = te + t * D_;
    const float* wq = Wq + (t * BASIS_ + warp) * D_;
    const float* wk = Wk + (t * BASIS_ + warp) * D_;
    float aq = 0.f, ak = 0.f;
    #pragma unroll
    for (int m = 0; m < D_ / 32; ++m) {
        int d = lane + 32 * m;
        float x = tr[d];
        aq += x * wq[d];
        ak += x * wk[d];
    }
    #pragma unroll
    for (int o = 16; o; o >>= 1) {
        aq += __shfl_xor_sync(0xffffffffu, aq, o);
        ak += __shfl_xor_sync(0xffffffffu, ak, o);
    }
    if (lane == 0) {
        g_qw[t * BASIS_ + warp] = aq;
        g_kw[t * BASIS_ + warp] = ak;
    }
}

// ---------------- K2: Q_tilde / K_tilde build (fp16 out), t-chunked ----------------
__global__ __launch_bounds__(256) void k2_tilde(const float* __restrict__ Qb,
                                                const float* __restrict__ Kb) {
    __shared__ float sW[64 * BASIS_];
    int qk = blockIdx.y;
    int t0 = blockIdx.z << 6;
    const float* W = (qk ? g_kw : g_qw) + t0 * BASIS_;
    const float* Bs = qk ? Kb : Qb;
    uint2* Out = qk ? (uint2*)g_Kt16 : (uint2*)g_Qt16;
    for (int idx = threadIdx.x; idx < 64 * BASIS_; idx += 256) sW[idx] = W[idx];
    __syncthreads();

    int f4 = blockIdx.x * 256 + threadIdx.x;
    float4 b4[BASIS_];
    #pragma unroll
    for (int k = 0; k < BASIS_; ++k) b4[k] = ((const float4*)Bs)[k * 16384 + f4];

    for (int tt = 0; tt < 64; ++tt) {
        float4 a = make_float4(0.f, 0.f, 0.f, 0.f);
        #pragma unroll
        for (int k = 0; k < BASIS_; ++k) {
            float w = sW[tt * BASIS_ + k];
            a.x += w * b4[k].x; a.y += w * b4[k].y;
            a.z += w * b4[k].z; a.w += w * b4[k].w;
        }
        __half2 h0 = __floats2half2_rn(a.x, a.y);
        __half2 h1 = __floats2half2_rn(a.z, a.w);
        uint2 u;
        u.x = *(const unsigned int*)&h0;
        u.y = *(const unsigned int*)&h1;
        Out[(t0 + tt) * 16384 + f4] = u;
    }
}

// ---------------- K3: q/k/v projections ----------------
// m=0: Q, m=1: K (8 cols/thread fp16 W); m=2/3: V col-halves (4 cols/thread fp32 W -> fp16 out)
__global__ __launch_bounds__(256) void k3_qkv(const float* __restrict__ X,
                                              const float* __restrict__ WV) {
    __shared__ float xsT[D_][16];
    int t = blockIdx.x, m = blockIdx.y;

    for (int idx = threadIdx.x; idx < B_ * D_; idx += 256) {
        int b = idx >> 8, d = idx & 255;
        xsT[d][b] = X[((size_t)b * T_ + t) * D_ + d];
    }
    __syncthreads();

    int tc = threadIdx.x & 31;
    int tb = threadIdx.x >> 5;   // 0..7 -> b pair

    if (m < 2) {
        float acc[2][8];
        #pragma unroll
        for (int i = 0; i < 2; ++i)
            #pragma unroll
            for (int j = 0; j < 8; ++j) acc[i][j] = 0.f;
        const uint4* W = (const uint4*)((m == 0 ? g_Qt16 : g_Kt16) + (size_t)t * 32768);
        #pragma unroll 8
        for (int d = 0; d < D_; ++d) {
            float2 xv = *(const float2*)&xsT[d][tb << 1];
            uint4 wr = W[(d << 5) + tc];
            float2 w0 = __half22float2(*(const __half2*)&wr.x);
            float2 w1 = __half22float2(*(const __half2*)&wr.y);
            float2 w2 = __half22float2(*(const __half2*)&wr.z);
            float2 w3 = __half22float2(*(const __half2*)&wr.w);
            acc[0][0] += xv.x * w0.x; acc[0][1] += xv.x * w0.y;
            acc[0][2] += xv.x * w1.x; acc[0][3] += xv.x * w1.y;
            acc[0][4] += xv.x * w2.x; acc[0][5] += xv.x * w2.y;
            acc[0][6] += xv.x * w3.x; acc[0][7] += xv.x * w3.y;
            acc[1][0] += xv.y * w0.x; acc[1][1] += xv.y * w0.y;
            acc[1][2] += xv.y * w1.x; acc[1][3] += xv.y * w1.y;
            acc[1][4] += xv.y * w2.x; acc[1][5] += xv.y * w2.y;
            acc[1][6] += xv.y * w3.x; acc[1][7] += xv.y * w3.y;
        }
        float* Out = (m == 0) ? g_q : g_k;
        int e0 = tc << 3;
        int h = e0 >> 5, eo = e0 & 31;
        #pragma unroll
        for (int i = 0; i < 2; ++i) {
            int b = (tb << 1) + i;
            size_t base = (((size_t)(h * B_ + b) * T_ + t) << 5) + eo;
            *(float4*)&g_q[0];  // no-op placeholder removed by compiler
            *(float4*)&Out[base]     = make_float4(acc[i][0], acc[i][1], acc[i][2], acc[i][3]);
            *(float4*)&Out[base + 4] = make_float4(acc[i][4], acc[i][5], acc[i][6], acc[i][7]);
        }
    } else {
        float acc[2][4];
        #pragma unroll
        for (int i = 0; i < 2; ++i)
            #pragma unroll
            for (int j = 0; j < 4; ++j) acc[i][j] = 0.f;
        int e0 = ((m - 2) << 7) + (tc << 2);
        const float* W = WV + (size_t)t * 65536;
        #pragma unroll 8
        for (int d = 0; d < D_; ++d) {
            float2 xv = *(const float2*)&xsT[d][tb << 1];
            float4 wv = *(const float4*)&W[(d << 8) + e0];
            acc[0][0] += xv.x * wv.x; acc[0][1] += xv.x * wv.y;
            acc[0][2] += xv.x * wv.z; acc[0][3] += xv.x * wv.w;
            acc[1][0] += xv.y * wv.x; acc[1][1] += xv.y * wv.y;
            acc[1][2] += xv.y * wv.z; acc[1][3] += xv.y * wv.w;
        }
        int h = e0 >> 5, eo = e0 & 31;
        #pragma unroll
        for (int i = 0; i < 2; ++i) {
            int b = (tb << 1) + i;
            __half2 h0 = __floats2half2_rn(acc[i][0], acc[i][1]);
            __half2 h1 = __floats2half2_rn(acc[i][2], acc[i][3]);
            uint2 u;
            u.x = *(const unsigned int*)&h0;
            u.y = *(const unsigned int*)&h1;
            *(uint2*)&g_v16[(((size_t)(h * B_ + b) * T_ + t) << 4) + (eo >> 1)] = u;
        }
    }
}

// ---------------- K4: mixing coefficients (half2 out) ----------------
__global__ void k4_mix(const float* __restrict__ A, const float* __restrict__ L) {
    int t = blockIdx.x, c = threadIdx.x;
    int j0 = c << 1, j1 = j0 + 1;
    float a0 = 0.5f * (A[t * T_ + j0] + A[j0 * T_ + t]);
    float a1 = 0.5f * (A[t * T_ + j1] + A[j1 * T_ + t]);
    float lam0 = 1.0f / (1.0f + __expf(-L[t * T_ + j0]));
    float lam1 = 1.0f / (1.0f + __expf(-L[t * T_ + j1]));
    g_lamA2[t * 256 + c] = __floats2half2_rn(lam0 * a0, lam1 * a1);
    g_oml2[t * 256 + c]  = __floats2half2_rn(1.0f - lam0, 1.0f - lam1);
}

// ---------------- K57: fused scores+softmax+mix+symexp+Sinkhorn+PV ----------------
// 4-CTA cluster per (h,b). CTA rank owns rows [128r,128r+128).
// smem: tile 131072 | union(kT2 65792 / Vs 65536) | s_y 4096 | s_ul 512
#define SM_UNION 131072
#define SM_Y     196864
#define SM_UL    200960
#define SMEM57   201472

#define CBAR() do { \
    asm volatile("barrier.cluster.arrive.aligned;" ::: "memory"); \
    asm volatile("barrier.cluster.wait.aligned;"  ::: "memory"); } while (0)

__global__ __launch_bounds__(512) __cluster_dims__(4, 1, 1)
void k57(float* __restrict__ out) {
    extern __shared__ char sm[];
    __half2* tile = (__half2*)sm;                 // [128][256] half2
    float2*  kT2  = (float2*)(sm + SM_UNION);     // [32][257] float2
    float*   Vs   = (float*)(sm + SM_UNION);      // [512][32] f32 (reuses kT2)
    float*   s_y  = (float*)(sm + SM_Y);          // [2][512]
    float*   s_ul = (float*)(sm + SM_UL);         // [128]

    int tid = threadIdx.x;
    int hb = blockIdx.x >> 2;
    int rank = blockIdx.x & 3;
    int warp = tid >> 5, lane = tid & 31;

    unsigned sbase;
    asm("{ .reg .u64 t; cvta.to.shared.u64 t, %1; cvt.u32.u64 %0, t; }"
        : "=r"(sbase) : "l"(sm));

    // ---- phase 1: K transpose into kT2 ----
    const float* K = g_k + hb * (T_ * E_);
    for (int idx = tid; idx < T_ * E_; idx += 512) {
        int t = idx >> 5, e = idx & 31;
        ((float*)&kT2[e * 257 + (t >> 1)])[t & 1] = K[idx];
    }
    __syncthreads();

    // ---- phase 2: scores + softmax + mix -> tile (fp16 M, local rows) ----
    {
        const float* Q = g_q + hb * (T_ * E_);
        const float SC = 0.17677669529663687f;
        for (int p = warp; p < 64; p += 16) {
            int i0 = p << 1, i1 = i0 + 1;                // local rows
            int gi0 = (rank << 7) + i0, gi1 = gi0 + 1;   // global rows
            float q0 = Q[(gi0 << 5) + lane];
            float q1 = Q[(gi1 << 5) + lane];
            float a[8][4];
            #pragma unroll
            for (int m = 0; m < 8; ++m) { a[m][0] = a[m][1] = a[m][2] = a[m][3] = 0.f; }
            #pragma unroll
            for (int d = 0; d < 32; ++d) {
                float qd0 = __shfl_sync(0xffffffffu, q0, d);
                float qd1 = __shfl_sync(0xffffffffu, q1, d);
                const float2* row = &kT2[d * 257];
                #pragma unroll
                for (int m = 0; m < 8; ++m) {
                    float2 kv = row[lane + (m << 5)];
                    a[m][0] += qd0 * kv.x; a[m][1] += qd0 * kv.y;
                    a[m][2] += qd1 * kv.x; a[m][3] += qd1 * kv.y;
                }
            }
            float mx0 = -1e30f, mx1 = -1e30f;
            #pragma unroll
            for (int m = 0; m < 8; ++m) {
                a[m][0] *= SC; a[m][1] *= SC; a[m][2] *= SC; a[m][3] *= SC;
                mx0 = fmaxf(mx0, fmaxf(a[m][0], a[m][1]));
                mx1 = fmaxf(mx1, fmaxf(a[m][2], a[m][3]));
            }
            #pragma unroll
            for (int o = 16; o; o >>= 1) {
                mx0 = fmaxf(mx0, __shfl_xor_sync(0xffffffffu, mx0, o));
                mx1 = fmaxf(mx1, __shfl_xor_sync(0xffffffffu, mx1, o));
            }
            float sm0 = 0.f, sm1 = 0.f;
            #pragma unroll
            for (int m = 0; m < 8; ++m) {
                a[m][0] = __expf(a[m][0] - mx0); a[m][1] = __expf(a[m][1] - mx0);
                a[m][2] = __expf(a[m][2] - mx1); a[m][3] = __expf(a[m][3] - mx1);
                sm0 += a[m][0] + a[m][1];
                sm1 += a[m][2] + a[m][3];
            }
            #pragma unroll
            for (int o = 16; o; o >>= 1) {
                sm0 += __shfl_xor_sync(0xffffffffu, sm0, o);
                sm1 += __shfl_xor_sync(0xffffffffu, sm1, o);
            }
            float in0 = 1.0f / sm0, in1 = 1.0f / sm1;
            #pragma unroll
            for (int m = 0; m < 8; ++m) {
                int c = lane + (m << 5);
                float2 la0 = __half22float2(g_lamA2[gi0 * 256 + c]);
                float2 om0 = __half22float2(g_oml2[gi0 * 256 + c]);
                float2 la1 = __half22float2(g_lamA2[gi1 * 256 + c]);
                float2 om1 = __half22float2(g_oml2[gi1 * 256 + c]);
                tile[(i0 << 8) + c] = __floats2half2_rn(la0.x + om0.x * (a[m][0] * in0),
                                                        la0.y + om0.y * (a[m][1] * in0));
                tile[(i1 << 8) + c] = __floats2half2_rn(la1.x + om1.x * (a[m][2] * in1),
                                                        la1.y + om1.y * (a[m][3] * in1));
            }
        }
    }
    __syncthreads();
    CBAR();   // all cluster tiles hold M

    // ---- phase 3: symmetrize + exp (DSMEM peer reads, reg-staged) ----
    {
        int i0 = (tid & 15) << 3;    // 8 rows
        int j0 = (tid >> 4) << 4;    // 16 cols
        uint4 pv[16];
        #pragma unroll
        for (int jj = 0; jj < 16; ++jj) {
            int j = j0 + jj;
            unsigned laddr = sbase + (unsigned)((((j & 127) << 9) + (rank << 7) + i0) << 1);
            unsigned raddr;
            asm volatile("mapa.shared::cluster.u32 %0, %1, %2;"
                         : "=r"(raddr) : "r"(laddr), "r"(j >> 7));
            asm volatile("ld.shared::cluster.v4.u32 {%0,%1,%2,%3}, [%4];"
                         : "=r"(pv[jj].x), "=r"(pv[jj].y), "=r"(pv[jj].z), "=r"(pv[jj].w)
                         : "r"(raddr));
        }
        CBAR();   // all reads done -> safe to overwrite
        #pragma unroll
        for (int ii = 0; ii < 8; ++ii) {
            int i = i0 + ii;
            __half2* rowp = &tile[(i << 8) + (j0 >> 1)];
            uint4 o0 = *(const uint4*)rowp;
            uint4 o1 = *(const uint4*)(rowp + 4);
            __half oh[16];
            *(uint4*)&oh[0] = o0;
            *(uint4*)&oh[8] = o1;
            __half rh[16];
            #pragma unroll
            for (int jj = 0; jj < 16; ++jj) {
                float pe = __half2float(((const __half*)&pv[jj])[ii]);
                float ow = __half2float(oh[jj]);
                rh[jj] = __float2half_rn(__expf(0.5f * (ow + pe)));
            }
            *(uint4*)rowp       = *(const uint4*)&rh[0];
            *(uint4*)(rowp + 4) = *(const uint4*)&rh[8];
        }
    }
    s_y[tid] = 1.0f;   // buffer 0 = ev_init
    __syncthreads();

    // ---- phase 4: Sinkhorn, 40 half-steps (u,v alternate; both are row ops by symmetry) ----
    int cur = 0;
    for (int hstep = 0; hstep < 40; ++hstep) {
        float2 yr[8];
        #pragma unroll
        for (int m = 0; m < 8; ++m)
            yr[m] = *(const float2*)&s_y[(cur << 9) + ((lane + (m << 5)) << 1)];
        int nxt = cur ^ 1;
        for (int i = warp; i < 128; i += 16) {
            const __half2* row = tile + (i << 8);
            float acc = 0.f;
            #pragma unroll
            for (int m = 0; m < 8; ++m) {
                float2 f = __half22float2(row[lane + (m << 5)]);
                acc += f.x * yr[m].x + f.y * yr[m].y;
            }
            #pragma unroll
            for (int o = 16; o; o >>= 1) acc += __shfl_xor_sync(0xffffffffu, acc, o);
            if (lane == 0) {
                float r = 1.0f / acc;
                if (!(hstep & 1)) s_ul[i] = r;
                unsigned laddr = sbase + (unsigned)(SM_Y + (((nxt << 9) + (rank << 7) + i) << 2));
                #pragma unroll
                for (int tr = 0; tr < 4; ++tr) {
                    unsigned raddr;
                    asm volatile("mapa.shared::cluster.u32 %0, %1, %2;"
                                 : "=r"(raddr) : "r"(laddr), "r"(tr));
                    asm volatile("st.shared::cluster.f32 [%0], %1;"
                                 :: "r"(raddr), "f"(r) : "memory");
                }
            }
        }
        CBAR();
        cur ^= 1;
    }
    // s_y[cur] = final ev (full 512), s_ul = final eu (local 128)

    // ---- phase 5: load V (fp16 global) scaled by ev -> Vs fp32 ----
    {
        const __half2* V16 = g_v16 + hb * 8192;
        for (int idx = tid; idx < 8192; idx += 512) {
            int j = idx >> 4, c2 = idx & 15;
            float2 v = __half22float2(V16[idx]);
            float e = s_y[(cur << 9) + j];
            Vs[(j << 5) + (c2 << 1)]     = v.x * e;
            Vs[(j << 5) + (c2 << 1) + 1] = v.y * e;
        }
    }
    __syncthreads();

    // ---- phase 6: out = eu * (E @ Vs) ----
    {
        float acc[8];
        #pragma unroll
        for (int r = 0; r < 8; ++r) acc[r] = 0.f;
        const __half2* trow = tile + ((warp << 3) << 8);
        #pragma unroll 2
        for (int c = 0; c < 256; ++c) {
            float vx = Vs[((c << 1) << 5) + lane];
            float vy = Vs[(((c << 1) + 1) << 5) + lane];
            #pragma unroll
            for (int r = 0; r < 8; ++r) {
                float2 p = __half22float2(trow[(r << 8) + c]);
                acc[r] += p.x * vx + p.y * vy;
            }
        }
        int h = hb >> 4, b = hb & 15;
        #pragma unroll
        for (int r = 0; r < 8; ++r) {
            int gi = (rank << 7) + (warp << 3) + r;
            out[(((size_t)(b * T_ + gi)) << 8) + (h << 5) + lane]
                = s_ul[(warp << 3) + r] * acc[r];
        }
    }
}

// ---------------- launch ----------------
extern "C" void kernel_launch(void* const* d_in, const int* in_sizes, int n_in,
                              void* d_out, int out_size) {
    const float* X  = (const float*)d_in[0];
    const float* te = (const float*)d_in[1];
    const float* Wq = (const float*)d_in[2];
    const float* Wk = (const float*)d_in[3];
    const float* Qb = (const float*)d_in[4];
    const float* Kb = (const float*)d_in[5];
    const float* WV = (const float*)d_in[6];
    const float* A  = (const float*)d_in[7];
    const float* L  = (const float*)d_in[8];
    float* out = (float*)d_out;

    cudaFuncSetAttribute(k57, cudaFuncAttributeMaxDynamicSharedMemorySize, SMEM57);

    k1_weights<<<T_, 256>>>(te, Wq, Wk);
    k2_tilde<<<dim3(64, 2, 8), 256>>>(Qb, Kb);
    k3_qkv<<<dim3(T_, 4), 256>>>(X, WV);
    k4_mix<<<T_, 256>>>(A, L);
    k57<<<HB_ * 4, 512, SMEM57>>>(out);
}